// round 11
// baseline (speedup 1.0000x reference)
#include <cuda_runtime.h>
#include <cstdint>

// ============================================================================
// CausalAttention, B=4, S=4096, D=1024, fp32 in/out.
// bf16x3-split mma.sync m16n8k16 GEMMs; hi/lo bf16x2 tiles in pair-line
// swizzled smem; ldmatrix.x4 fragment loads. 256 thr/CTA, 4x2 warps, 32x64
// warp tiles, double buffer — REGISTER-LEAN variant targeting 2 CTAs/SM
// (__launch_bounds__(256,2)): B fragments loaded per ni-pair, no gmem
// prefetch registers (co-resident CTA hides LDG latency).
// ============================================================================

static constexpr int Bb = 4;
static constexpr int S  = 4096;
static constexpr int D  = 1024;
static constexpr int BM = 128;
static constexpr int BN = 128;
static constexpr int BK = 32;                 // floats per chunk (16 words)

static constexpr int TILE_W    = 2048;        // words per [128][16] tile (8 KB)
static constexpr int STAGE_W   = 4 * TILE_W;  // Ah, Al, Bh, Bl
static constexpr int SMEM_BYTES = 2 * STAGE_W * 4;   // 65536

static __device__ float g_q [(size_t)Bb * S * D];
static __device__ float g_k [(size_t)Bb * S * D];
static __device__ float g_v [(size_t)Bb * S * D];
static __device__ float g_vt[(size_t)Bb * D * S];
static __device__ float g_wt[(size_t)3 * D * D];
static __device__ float g_s [(size_t)Bb * S * S];

// ---------------------------------------------------------------------------
__device__ __forceinline__ uint32_t tile_addr(uint32_t row, uint32_t w) {
    const uint32_t line = row >> 1;
    const uint32_t off  = ((row & 1u) << 4) + w;
    return line * 32u + (off ^ ((line & 7u) << 2));
}

__device__ __forceinline__ uint32_t smem_u32(const void* p) {
    uint32_t a;
    asm("{ .reg .u64 t; cvta.to.shared.u64 t, %1; cvt.u32.u64 %0, t; }"
        : "=r"(a) : "l"(p));
    return a;
}

__device__ __forceinline__ void ldsm_x4(uint32_t (&r)[4], uint32_t saddr) {
    asm volatile("ldmatrix.sync.aligned.m8n8.x4.shared.b16 {%0,%1,%2,%3}, [%4];"
                 : "=r"(r[0]), "=r"(r[1]), "=r"(r[2]), "=r"(r[3])
                 : "r"(saddr));
}

// split (x0, x1) into hi/lo bf16x2 words (lower 16 bits = x0)
__device__ __forceinline__ void bf16_split2(float x0, float x1,
                                            uint32_t& hw, uint32_t& lw) {
    asm("cvt.rn.bf16x2.f32 %0, %1, %2;" : "=r"(hw) : "f"(x1), "f"(x0));
    const float h0 = __uint_as_float(hw << 16);
    const float h1 = __uint_as_float(hw & 0xffff0000u);
    const float r0 = x0 - h0;
    const float r1 = x1 - h1;
    asm("cvt.rn.bf16x2.f32 %0, %1, %2;" : "=r"(lw) : "f"(r1), "f"(r0));
}

__device__ __forceinline__ void mma_bf16(float (&d)[4], const uint32_t (&a)[4],
                                         uint32_t b0, uint32_t b1) {
    asm("mma.sync.aligned.m16n8k16.row.col.f32.bf16.bf16.f32 "
        "{%0,%1,%2,%3}, {%4,%5,%6,%7}, {%8,%9}, {%0,%1,%2,%3};"
        : "+f"(d[0]), "+f"(d[1]), "+f"(d[2]), "+f"(d[3])
        : "r"(a[0]), "r"(a[1]), "r"(a[2]), "r"(a[3]), "r"(b0), "r"(b1));
}

__device__ __forceinline__ void stage_half(uint32_t* hiT, uint32_t* loT,
                                           uint32_t i0, const float4 f[4]) {
    uint4 h0, h1, l0, l1;
    bf16_split2(f[0].x, f[0].y, h0.x, l0.x);
    bf16_split2(f[0].z, f[0].w, h0.y, l0.y);
    bf16_split2(f[1].x, f[1].y, h0.z, l0.z);
    bf16_split2(f[1].z, f[1].w, h0.w, l0.w);
    bf16_split2(f[2].x, f[2].y, h1.x, l1.x);
    bf16_split2(f[2].z, f[2].w, h1.y, l1.y);
    bf16_split2(f[3].x, f[3].y, h1.z, l1.z);
    bf16_split2(f[3].z, f[3].w, h1.w, l1.w);
    *(uint4*)(hiT + i0)        = h0;
    *(uint4*)(hiT + (i0 ^ 4u)) = h1;
    *(uint4*)(loT + i0)        = l0;
    *(uint4*)(loT + (i0 ^ 4u)) = l1;
}

// stage one chunk (A half + B half for this thread) into stage buffer S
__device__ __forceinline__ void stage_chunk(uint32_t* Sb, uint32_t stA,
                                            const float* ap, const float* bp) {
    float4 f[4];
    #pragma unroll
    for (int i = 0; i < 4; i++) f[i] = *(const float4*)(ap + i * 4);
    stage_half(Sb, Sb + TILE_W, stA, f);
    #pragma unroll
    for (int i = 0; i < 4; i++) f[i] = *(const float4*)(bp + i * 4);
    stage_half(Sb + 2 * TILE_W, Sb + 3 * TILE_W, stA, f);
}

// ---------------------------------------------------------------------------
// C[bm,bn tile] = A(MxK, lda, row-major) * B^T, B is [N,K] row-major (ldb).
// 256 threads, register-lean (target 2 CTAs/SM). KLIM: K limited to (bm+1)*BM.
// ---------------------------------------------------------------------------
template<bool KLIM>
__device__ __forceinline__ void
gemm_core(const float* __restrict__ A, const float* __restrict__ Bm,
          float* __restrict__ C, int N, int K, int lda, int ldb,
          int bm, int bn)
{
    const int kEnd   = KLIM ? min(K, (bm + 1) * BM) : K;
    const int nchunk = kEnd / BK;

    extern __shared__ uint32_t sm[];
    const uint32_t smb = smem_u32(sm);

    const int tid  = threadIdx.x;
    const int wid  = tid >> 5;
    const int wm   = wid & 3;               // 4 warps along M
    const int wn   = wid >> 2;              // 2 warps along N
    const int lane = tid & 31;
    const int g    = lane >> 2;
    const int c    = lane & 3;
    const int l8   = lane & 7;
    const int lm   = lane >> 3;             // ldmatrix matrix id 0..3

    // A frag addresses: [mi][kt]; B frag base for p=0, [kt]; p stride = 1024 B
    uint32_t relA[2][2], relB0[2];
    #pragma unroll
    for (int mi = 0; mi < 2; mi++) {
        const uint32_t row = wm * 32 + mi * 16 + ((lm & 1) << 3) + l8;
        const uint32_t w   = (lm >> 1) << 2;
        relA[mi][0] = tile_addr(row, w) * 4u;
        relA[mi][1] = tile_addr(row, w + 8) * 4u;
    }
    {
        const uint32_t row = wn * 64 + ((lm >> 1) << 3) + l8;
        const uint32_t w   = (lm & 1) << 2;
        relB0[0] = tile_addr(row, w) * 4u;
        relB0[1] = tile_addr(row, w + 8) * 4u;
    }

    // staging map: thread t -> row t>>1, k-half h = t&1 (16 floats)
    const int srow = tid >> 1;
    const int h    = tid & 1;
    const uint32_t stA = tile_addr(srow, h * 8);
    const float* Ap = A + (long long)(bm * BM + srow) * lda + h * 16;
    const float* Bp = Bm + (long long)(bn * BN + srow) * ldb + h * 16;

    // stage chunk 0
    stage_chunk(sm, stA, Ap, Bp);
    __syncthreads();

    float acc[2][8][4];
    #pragma unroll
    for (int mi = 0; mi < 2; mi++)
        #pragma unroll
        for (int ni = 0; ni < 8; ni++)
            #pragma unroll
            for (int q = 0; q < 4; q++) acc[mi][ni][q] = 0.f;

    for (int ic = 0; ic < nchunk; ic++) {
        const int st = ic & 1;
        const uint32_t bAh = smb + st * (STAGE_W * 4);
        const uint32_t bAl = bAh + TILE_W * 4;
        const uint32_t bBh = bAh + 2 * (TILE_W * 4);
        const uint32_t bBl = bAh + 3 * (TILE_W * 4);

        #pragma unroll
        for (int kt = 0; kt < 2; kt++) {
            uint32_t ah[2][4], al[2][4];
            #pragma unroll
            for (int mi = 0; mi < 2; mi++) {
                ldsm_x4(ah[mi], bAh + relA[mi][kt]);
                ldsm_x4(al[mi], bAl + relA[mi][kt]);
            }
            #pragma unroll
            for (int p = 0; p < 4; p++) {
                uint32_t bh[4], bl[4];
                ldsm_x4(bh, bBh + relB0[kt] + p * 1024u);
                ldsm_x4(bl, bBl + relB0[kt] + p * 1024u);
                const int n0 = 2 * p, n1 = 2 * p + 1;
                // grouped by split term; 4 distinct accumulators per group
                mma_bf16(acc[0][n0], ah[0], bh[0], bh[1]);
                mma_bf16(acc[0][n1], ah[0], bh[2], bh[3]);
                mma_bf16(acc[1][n0], ah[1], bh[0], bh[1]);
                mma_bf16(acc[1][n1], ah[1], bh[2], bh[3]);
                mma_bf16(acc[0][n0], al[0], bh[0], bh[1]);
                mma_bf16(acc[0][n1], al[0], bh[2], bh[3]);
                mma_bf16(acc[1][n0], al[1], bh[0], bh[1]);
                mma_bf16(acc[1][n1], al[1], bh[2], bh[3]);
                mma_bf16(acc[0][n0], ah[0], bl[0], bl[1]);
                mma_bf16(acc[0][n1], ah[0], bl[2], bl[3]);
                mma_bf16(acc[1][n0], ah[1], bl[0], bl[1]);
                mma_bf16(acc[1][n1], ah[1], bl[2], bl[3]);
            }
        }

        // stage chunk ic+1 into the other buffer (its readers passed the
        // previous sync); LDG latency here is hidden by the co-resident CTA
        if (ic + 1 < nchunk) {
            stage_chunk(sm + (st ^ 1) * STAGE_W, stA,
                        Ap + (ic + 1) * BK, Bp + (ic + 1) * BK);
        }
        __syncthreads();
    }

    // epilogue
    #pragma unroll
    for (int mi = 0; mi < 2; mi++) {
        const int r0 = bm * BM + wm * 32 + mi * 16 + g;
        #pragma unroll
        for (int ni = 0; ni < 8; ni++) {
            const int cc = bn * BN + wn * 64 + ni * 8 + c * 2;
            float2 v0 = make_float2(acc[mi][ni][0], acc[mi][ni][1]);
            float2 v1 = make_float2(acc[mi][ni][2], acc[mi][ni][3]);
            *(float2*)(C + (long long)r0 * N + cc)       = v0;
            *(float2*)(C + (long long)(r0 + 8) * N + cc) = v1;
        }
    }
}

// ---- kernels ---------------------------------------------------------------
__global__ void __launch_bounds__(256, 2)
k_qkv(const float* __restrict__ x, const float* __restrict__ wt,
      float* __restrict__ q, float* __restrict__ k, float* __restrict__ v)
{
    const float* W = wt + (size_t)blockIdx.z * D * D;   // W^T: [d_out][d_in]
    float* out = blockIdx.z == 0 ? q : (blockIdx.z == 1 ? k : v);
    gemm_core<false>(x, W, out, D, D, D, D, blockIdx.y, blockIdx.x);
}

__global__ void __launch_bounds__(256, 2)
k_scores(const float* __restrict__ q, const float* __restrict__ kk,
         float* __restrict__ sc)
{
    if ((int)blockIdx.x > (int)blockIdx.y) return;      // causal block skip
    const size_t z = blockIdx.z;
    gemm_core<false>(q + z * (size_t)S * D, kk + z * (size_t)S * D,
                     sc + z * (size_t)S * S, S, D, D, D, blockIdx.y, blockIdx.x);
}

__global__ void __launch_bounds__(256, 2)
k_pv(const float* __restrict__ sc, const float* __restrict__ vt,
     float* __restrict__ out)
{
    const size_t z = blockIdx.z;
    gemm_core<true>(sc + z * (size_t)S * S, vt + z * (size_t)D * S,
                    out + z * (size_t)S * D, D, S, S, S,
                    blockIdx.y, blockIdx.x);
}

// ---- transposes ------------------------------------------------------------
__global__ void __launch_bounds__(256)
k_wt(const float* __restrict__ wq, const float* __restrict__ wk,
     const float* __restrict__ wv, float* __restrict__ wt)
{
    __shared__ float t[32][33];
    const float* src = blockIdx.z == 0 ? wq : (blockIdx.z == 1 ? wk : wv);
    float* dst = wt + (size_t)blockIdx.z * D * D;
    const int r0 = blockIdx.x << 5, c0 = blockIdx.y << 5;
    const int tx = threadIdx.x & 31, ty = threadIdx.x >> 5;
    #pragma unroll
    for (int i = 0; i < 32; i += 8)
        t[ty + i][tx] = src[(size_t)(r0 + ty + i) * D + c0 + tx];
    __syncthreads();
    #pragma unroll
    for (int i = 0; i < 32; i += 8)
        dst[(size_t)(c0 + ty + i) * D + r0 + tx] = t[tx][ty + i];
}

__global__ void __launch_bounds__(256)
k_vt(const float* __restrict__ v, float* __restrict__ vt)
{
    __shared__ float t[32][33];
    const float* sp = v  + (size_t)blockIdx.z * S * D;
    float*       dp = vt + (size_t)blockIdx.z * D * S;
    const int s0 = blockIdx.x << 5, d0 = blockIdx.y << 5;
    const int tx = threadIdx.x & 31, ty = threadIdx.x >> 5;
    #pragma unroll
    for (int i = 0; i < 32; i += 8)
        t[ty + i][tx] = sp[(size_t)(s0 + ty + i) * D + d0 + tx];
    __syncthreads();
    #pragma unroll
    for (int i = 0; i < 32; i += 8)
        dp[(size_t)(d0 + ty + i) * S + s0 + tx] = t[tx][ty + i];
}

// ---- softmax ---------------------------------------------------------------
__global__ void __launch_bounds__(256)
softmax_causal(float* __restrict__ sc)
{
    const int r = blockIdx.x;
    const int b = r >> 12;
    const int i = r & (S - 1);
    float* row = sc + ((long long)b * S * S) + ((long long)i * S);
    const int n  = i + 1;
    const int n4 = n & ~3;
    const int tid  = threadIdx.x;
    const int wid  = tid >> 5;
    const int lane = tid & 31;
    const float scale = 0.03125f;   // 1/sqrt(1024)

    __shared__ float shm[8], shs[8];

    auto upd = [&](float& m, float& s, float v) {
        if (v <= m) s += __expf((v - m) * scale);
        else { s = s * __expf((m - v) * scale) + 1.f; m = v; }
    };

    float m = -3.0e38f, s = 0.f;
    for (int j = tid * 4; j < n4; j += 1024) {
        float4 vv = *(const float4*)(row + j);
        upd(m, s, vv.x); upd(m, s, vv.y); upd(m, s, vv.z); upd(m, s, vv.w);
    }
    for (int j = n4 + tid; j < n; j += 256) upd(m, s, row[j]);

    #pragma unroll
    for (int o = 16; o > 0; o >>= 1) {
        float mo = __shfl_xor_sync(0xffffffffu, m, o);
        float so = __shfl_xor_sync(0xffffffffu, s, o);
        float M  = fmaxf(m, mo);
        s = s * __expf((m - M) * scale) + so * __expf((mo - M) * scale);
        m = M;
    }
    if (lane == 0) { shm[wid] = m; shs[wid] = s; }
    __syncthreads();
    float M = shm[0], Sm = shs[0];
    #pragma unroll
    for (int t = 1; t < 8; t++) {
        float mo = shm[t], so = shs[t];
        float Mx = fmaxf(M, mo);
        Sm = Sm * __expf((M - Mx) * scale) + so * __expf((mo - Mx) * scale);
        M = Mx;
    }
    const float inv = 1.0f / Sm;

    for (int j = tid * 4; j < n4; j += 1024) {
        float4 vv = *(const float4*)(row + j);
        vv.x = __expf((vv.x - M) * scale) * inv;
        vv.y = __expf((vv.y - M) * scale) * inv;
        vv.z = __expf((vv.z - M) * scale) * inv;
        vv.w = __expf((vv.w - M) * scale) * inv;
        *(float4*)(row + j) = vv;
    }
    for (int j = n4 + tid; j < n; j += 256)
        row[j] = __expf((row[j] - M) * scale) * inv;

    const int end = ((i >> 7) + 1) << 7;
    for (int j = n + tid; j < end; j += 256) row[j] = 0.f;
}

// ---------------------------------------------------------------------------
extern "C" void kernel_launch(void* const* d_in, const int* in_sizes, int n_in,
                              void* d_out, int out_size)
{
    const float* x  = (const float*)d_in[0];
    const float* Wq = (const float*)d_in[1];
    const float* Wk = (const float*)d_in[2];
    const float* Wv = (const float*)d_in[3];
    float* out = (float*)d_out;

    static float *q = nullptr, *k = nullptr, *v = nullptr, *vt = nullptr,
                 *wt = nullptr, *sc = nullptr;
    static bool init = false;
    if (!init) {
        cudaGetSymbolAddress((void**)&q,  g_q);
        cudaGetSymbolAddress((void**)&k,  g_k);
        cudaGetSymbolAddress((void**)&v,  g_v);
        cudaGetSymbolAddress((void**)&vt, g_vt);
        cudaGetSymbolAddress((void**)&wt, g_wt);
        cudaGetSymbolAddress((void**)&sc, g_s);
        cudaFuncSetAttribute(k_qkv,
                             cudaFuncAttributeMaxDynamicSharedMemorySize, SMEM_BYTES);
        cudaFuncSetAttribute(k_scores,
                             cudaFuncAttributeMaxDynamicSharedMemorySize, SMEM_BYTES);
        cudaFuncSetAttribute(k_pv,
                             cudaFuncAttributeMaxDynamicSharedMemorySize, SMEM_BYTES);
        init = true;
    }

    // 1) W^T (B operand is [N,K] = [d_out][d_in])
    k_wt<<<dim3(D / 32, D / 32, 3), 256>>>(Wq, Wk, Wv, wt);

    // 2) QKV projections
    k_qkv<<<dim3(D / BN, (Bb * S) / BM, 3), 256, SMEM_BYTES>>>(x, wt, q, k, v);

    // 3) V^T for PV
    k_vt<<<dim3(S / 32, D / 32, Bb), 256>>>(v, vt);

    // 4) scores = Q K^T  (K's natural [S,D] layout is the [N,K] operand)
    k_scores<<<dim3(S / BN, S / BM, Bb), 256, SMEM_BYTES>>>(q, k, sc);

    // 5) softmax
    softmax_causal<<<Bb * S, 256>>>(sc);

    // 6) out = P V  (B = V^T)
    k_pv<<<dim3(D / BN, S / BM, Bb), 256, SMEM_BYTES>>>(sc, vt, out);
}

// round 12
// speedup vs baseline: 1.2837x; 1.2837x over previous
#include <cuda_runtime.h>
#include <cstdint>

// ============================================================================
// CausalAttention, B=4, S=4096, D=1024, fp32 in/out.
// bf16x3-split mma.sync m16n8k16 GEMMs. KEY CHANGE (R12): block tile 256x128
// with 64x64 warp tiles (4x2 warps) — cuts shared-memory crossbar bytes per
// MMA by ~31% vs 32x64 (crossbar was measured as the binding resource).
// Pair-line swizzled hi/lo bf16x2 tiles, ldmatrix.x4 fragments, double buffer,
// one __syncthreads per 32-K chunk, 1 CTA/SM.
// ============================================================================

static constexpr int Bb = 4;
static constexpr int S  = 4096;
static constexpr int D  = 1024;
static constexpr int BM = 256;
static constexpr int BN = 128;
static constexpr int BK = 32;                 // floats per chunk (16 words)

static constexpr int TILE_A_W  = BM * 16;     // 4096 words (16 KB)
static constexpr int TILE_B_W  = BN * 16;     // 2048 words (8 KB)
static constexpr int OFF_AH = 0;
static constexpr int OFF_AL = TILE_A_W;               // 4096
static constexpr int OFF_BH = 2 * TILE_A_W;           // 8192
static constexpr int OFF_BL = 2 * TILE_A_W + TILE_B_W;// 10240
static constexpr int STAGE_W = 2 * TILE_A_W + 2 * TILE_B_W;   // 12288 words
static constexpr int SMEM_BYTES = 2 * STAGE_W * 4;            // 98304 B

static __device__ float g_q [(size_t)Bb * S * D];
static __device__ float g_k [(size_t)Bb * S * D];
static __device__ float g_v [(size_t)Bb * S * D];
static __device__ float g_vt[(size_t)Bb * D * S];
static __device__ float g_wt[(size_t)3 * D * D];
static __device__ float g_s [(size_t)Bb * S * S];

// ---------------------------------------------------------------------------
__device__ __forceinline__ uint32_t tile_addr(uint32_t row, uint32_t w) {
    const uint32_t line = row >> 1;
    const uint32_t off  = ((row & 1u) << 4) + w;
    return line * 32u + (off ^ ((line & 7u) << 2));
}

__device__ __forceinline__ uint32_t smem_u32(const void* p) {
    uint32_t a;
    asm("{ .reg .u64 t; cvta.to.shared.u64 t, %1; cvt.u32.u64 %0, t; }"
        : "=r"(a) : "l"(p));
    return a;
}

__device__ __forceinline__ void ldsm_x4(uint32_t (&r)[4], uint32_t saddr) {
    asm volatile("ldmatrix.sync.aligned.m8n8.x4.shared.b16 {%0,%1,%2,%3}, [%4];"
                 : "=r"(r[0]), "=r"(r[1]), "=r"(r[2]), "=r"(r[3])
                 : "r"(saddr));
}

// split (x0, x1) into hi/lo bf16x2 words (lower 16 bits = x0)
__device__ __forceinline__ void bf16_split2(float x0, float x1,
                                            uint32_t& hw, uint32_t& lw) {
    asm("cvt.rn.bf16x2.f32 %0, %1, %2;" : "=r"(hw) : "f"(x1), "f"(x0));
    const float h0 = __uint_as_float(hw << 16);
    const float h1 = __uint_as_float(hw & 0xffff0000u);
    const float r0 = x0 - h0;
    const float r1 = x1 - h1;
    asm("cvt.rn.bf16x2.f32 %0, %1, %2;" : "=r"(lw) : "f"(r1), "f"(r0));
}

__device__ __forceinline__ void mma_bf16(float (&d)[4], const uint32_t (&a)[4],
                                         uint32_t b0, uint32_t b1) {
    asm("mma.sync.aligned.m16n8k16.row.col.f32.bf16.bf16.f32 "
        "{%0,%1,%2,%3}, {%4,%5,%6,%7}, {%8,%9}, {%0,%1,%2,%3};"
        : "+f"(d[0]), "+f"(d[1]), "+f"(d[2]), "+f"(d[3])
        : "r"(a[0]), "r"(a[1]), "r"(a[2]), "r"(a[3]), "r"(b0), "r"(b1));
}

__device__ __forceinline__ void stage_half(uint32_t* hiT, uint32_t* loT,
                                           uint32_t i0, const float4 f[4]) {
    uint4 h0, h1, l0, l1;
    bf16_split2(f[0].x, f[0].y, h0.x, l0.x);
    bf16_split2(f[0].z, f[0].w, h0.y, l0.y);
    bf16_split2(f[1].x, f[1].y, h0.z, l0.z);
    bf16_split2(f[1].z, f[1].w, h0.w, l0.w);
    bf16_split2(f[2].x, f[2].y, h1.x, l1.x);
    bf16_split2(f[2].z, f[2].w, h1.y, l1.y);
    bf16_split2(f[3].x, f[3].y, h1.z, l1.z);
    bf16_split2(f[3].z, f[3].w, h1.w, l1.w);
    *(uint4*)(hiT + i0)        = h0;
    *(uint4*)(hiT + (i0 ^ 4u)) = h1;
    *(uint4*)(loT + i0)        = l0;
    *(uint4*)(loT + (i0 ^ 4u)) = l1;
}

// ---------------------------------------------------------------------------
// C[bm*256.., bn*128..] = A(MxK, lda) * B^T, B is [N,K] row-major (ldb).
// 256 threads, 4x2 warps of 64x64. KLIM: K limited to (bm+1)*BM.
// ---------------------------------------------------------------------------
template<bool KLIM>
__device__ __forceinline__ void
gemm_core(const float* __restrict__ A, const float* __restrict__ Bm,
          float* __restrict__ C, int N, int K, int lda, int ldb,
          int bm, int bn)
{
    const int kEnd   = KLIM ? min(K, (bm + 1) * BM) : K;
    const int nchunk = kEnd / BK;

    extern __shared__ uint32_t sm[];
    const uint32_t smb = smem_u32(sm);

    const int tid  = threadIdx.x;
    const int wid  = tid >> 5;
    const int wm   = wid & 3;               // 4 warps along M (64 rows each)
    const int wn   = wid >> 2;              // 2 warps along N (64 cols each)
    const int lane = tid & 31;
    const int g    = lane >> 2;
    const int c    = lane & 3;
    const int l8   = lane & 7;
    const int lm   = lane >> 3;             // ldmatrix matrix id 0..3

    // fragment addresses (bytes, relative to stage base)
    uint32_t relA[4][2], relB0[2];
    #pragma unroll
    for (int mi = 0; mi < 4; mi++) {
        const uint32_t row = wm * 64 + mi * 16 + ((lm & 1) << 3) + l8;
        const uint32_t w   = (lm >> 1) << 2;
        relA[mi][0] = tile_addr(row, w) * 4u;
        relA[mi][1] = tile_addr(row, w + 8) * 4u;
    }
    {
        const uint32_t row = wn * 64 + ((lm >> 1) << 3) + l8;
        const uint32_t w   = (lm & 1) << 2;
        relB0[0] = tile_addr(row, w) * 4u;
        relB0[1] = tile_addr(row, w + 8) * 4u;
    }

    // staging map: thread t -> row t>>1 (+128 for 2nd A pass), half h = t&1
    const int srow = tid >> 1;
    const int h    = tid & 1;
    const uint32_t st0 = tile_addr(srow, h * 8);
    const uint32_t st1 = tile_addr(srow + 128, h * 8);
    const float* Ap0 = A + (long long)(bm * BM + srow) * lda + h * 16;
    const float* Ap1 = Ap0 + (long long)128 * lda;
    const float* Bp  = Bm + (long long)(bn * BN + srow) * ldb + h * 16;

    auto stage_chunk = [&](uint32_t* Sb, int kc) {
        float4 f[4];
        const float* a0 = Ap0 + kc;
        const float* a1 = Ap1 + kc;
        const float* bp = Bp + kc;
        #pragma unroll
        for (int i = 0; i < 4; i++) f[i] = *(const float4*)(a0 + i * 4);
        stage_half(Sb + OFF_AH, Sb + OFF_AL, st0, f);
        #pragma unroll
        for (int i = 0; i < 4; i++) f[i] = *(const float4*)(a1 + i * 4);
        stage_half(Sb + OFF_AH, Sb + OFF_AL, st1, f);
        #pragma unroll
        for (int i = 0; i < 4; i++) f[i] = *(const float4*)(bp + i * 4);
        stage_half(Sb + OFF_BH, Sb + OFF_BL, st0, f);
    };

    stage_chunk(sm, 0);
    __syncthreads();

    float acc[4][8][4];
    #pragma unroll
    for (int mi = 0; mi < 4; mi++)
        #pragma unroll
        for (int ni = 0; ni < 8; ni++)
            #pragma unroll
            for (int q = 0; q < 4; q++) acc[mi][ni][q] = 0.f;

    for (int ic = 0; ic < nchunk; ic++) {
        const int st = ic & 1;
        const uint32_t base = smb + st * (STAGE_W * 4);
        const uint32_t bAh = base + OFF_AH * 4;
        const uint32_t bAl = base + OFF_AL * 4;
        const uint32_t bBh = base + OFF_BH * 4;
        const uint32_t bBl = base + OFF_BL * 4;

        #pragma unroll
        for (int kt = 0; kt < 2; kt++) {
            uint32_t ah[4][4], al[4][4];
            #pragma unroll
            for (int mi = 0; mi < 4; mi++) {
                ldsm_x4(ah[mi], bAh + relA[mi][kt]);
                ldsm_x4(al[mi], bAl + relA[mi][kt]);
            }
            #pragma unroll
            for (int p = 0; p < 4; p++) {
                uint32_t bh[4], bl[4];
                ldsm_x4(bh, bBh + relB0[kt] + p * 1024u);
                ldsm_x4(bl, bBl + relB0[kt] + p * 1024u);
                const int n0 = 2 * p, n1 = 2 * p + 1;
                // hh term (8 distinct accumulators)
                #pragma unroll
                for (int mi = 0; mi < 4; mi++) {
                    mma_bf16(acc[mi][n0], ah[mi], bh[0], bh[1]);
                    mma_bf16(acc[mi][n1], ah[mi], bh[2], bh[3]);
                }
                // lh term
                #pragma unroll
                for (int mi = 0; mi < 4; mi++) {
                    mma_bf16(acc[mi][n0], al[mi], bh[0], bh[1]);
                    mma_bf16(acc[mi][n1], al[mi], bh[2], bh[3]);
                }
                // hl term
                #pragma unroll
                for (int mi = 0; mi < 4; mi++) {
                    mma_bf16(acc[mi][n0], ah[mi], bl[0], bl[1]);
                    mma_bf16(acc[mi][n1], ah[mi], bl[2], bl[3]);
                }
            }
        }

        if (ic + 1 < nchunk)
            stage_chunk(sm + (st ^ 1) * STAGE_W, (ic + 1) * BK);
        __syncthreads();
    }

    // epilogue
    #pragma unroll
    for (int mi = 0; mi < 4; mi++) {
        const int r0 = bm * BM + wm * 64 + mi * 16 + g;
        #pragma unroll
        for (int ni = 0; ni < 8; ni++) {
            const int cc = bn * BN + wn * 64 + ni * 8 + c * 2;
            float2 v0 = make_float2(acc[mi][ni][0], acc[mi][ni][1]);
            float2 v1 = make_float2(acc[mi][ni][2], acc[mi][ni][3]);
            *(float2*)(C + (long long)r0 * N + cc)       = v0;
            *(float2*)(C + (long long)(r0 + 8) * N + cc) = v1;
        }
    }
}

// ---- kernels ---------------------------------------------------------------
__global__ void __launch_bounds__(256, 1)
k_qkv(const float* __restrict__ x, const float* __restrict__ wt,
      float* __restrict__ q, float* __restrict__ k, float* __restrict__ v)
{
    const float* W = wt + (size_t)blockIdx.z * D * D;   // W^T: [d_out][d_in]
    float* out = blockIdx.z == 0 ? q : (blockIdx.z == 1 ? k : v);
    gemm_core<false>(x, W, out, D, D, D, D, blockIdx.y, blockIdx.x);
}

__global__ void __launch_bounds__(256, 1)
k_scores(const float* __restrict__ q, const float* __restrict__ kk,
         float* __restrict__ sc)
{
    const int bm = blockIdx.y, bn = blockIdx.x;
    if (bn > 2 * bm + 1) return;            // block fully above diagonal
    const size_t z = blockIdx.z;
    gemm_core<false>(q + z * (size_t)S * D, kk + z * (size_t)S * D,
                     sc + z * (size_t)S * S, S, D, D, D, bm, bn);
}

__global__ void __launch_bounds__(256, 1)
k_pv(const float* __restrict__ sc, const float* __restrict__ vt,
     float* __restrict__ out)
{
    const size_t z = blockIdx.z;
    gemm_core<true>(sc + z * (size_t)S * S, vt + z * (size_t)D * S,
                    out + z * (size_t)S * D, D, S, S, S,
                    blockIdx.y, blockIdx.x);
}

// ---- transposes ------------------------------------------------------------
__global__ void __launch_bounds__(256)
k_wt(const float* __restrict__ wq, const float* __restrict__ wk,
     const float* __restrict__ wv, float* __restrict__ wt)
{
    __shared__ float t[32][33];
    const float* src = blockIdx.z == 0 ? wq : (blockIdx.z == 1 ? wk : wv);
    float* dst = wt + (size_t)blockIdx.z * D * D;
    const int r0 = blockIdx.x << 5, c0 = blockIdx.y << 5;
    const int tx = threadIdx.x & 31, ty = threadIdx.x >> 5;
    #pragma unroll
    for (int i = 0; i < 32; i += 8)
        t[ty + i][tx] = src[(size_t)(r0 + ty + i) * D + c0 + tx];
    __syncthreads();
    #pragma unroll
    for (int i = 0; i < 32; i += 8)
        dst[(size_t)(c0 + ty + i) * D + r0 + tx] = t[tx][ty + i];
}

__global__ void __launch_bounds__(256)
k_vt(const float* __restrict__ v, float* __restrict__ vt)
{
    __shared__ float t[32][33];
    const float* sp = v  + (size_t)blockIdx.z * S * D;
    float*       dp = vt + (size_t)blockIdx.z * D * S;
    const int s0 = blockIdx.x << 5, d0 = blockIdx.y << 5;
    const int tx = threadIdx.x & 31, ty = threadIdx.x >> 5;
    #pragma unroll
    for (int i = 0; i < 32; i += 8)
        t[ty + i][tx] = sp[(size_t)(s0 + ty + i) * D + d0 + tx];
    __syncthreads();
    #pragma unroll
    for (int i = 0; i < 32; i += 8)
        dp[(size_t)(d0 + ty + i) * S + s0 + tx] = t[tx][ty + i];
}

// ---- softmax ---------------------------------------------------------------
__global__ void __launch_bounds__(256)
softmax_causal(float* __restrict__ sc)
{
    const int r = blockIdx.x;
    const int b = r >> 12;
    const int i = r & (S - 1);
    float* row = sc + ((long long)b * S * S) + ((long long)i * S);
    const int n  = i + 1;
    const int n4 = n & ~3;
    const int tid  = threadIdx.x;
    const int wid  = tid >> 5;
    const int lane = tid & 31;
    const float scale = 0.03125f;   // 1/sqrt(1024)

    __shared__ float shm[8], shs[8];

    auto upd = [&](float& m, float& s, float v) {
        if (v <= m) s += __expf((v - m) * scale);
        else { s = s * __expf((m - v) * scale) + 1.f; m = v; }
    };

    float m = -3.0e38f, s = 0.f;
    for (int j = tid * 4; j < n4; j += 1024) {
        float4 vv = *(const float4*)(row + j);
        upd(m, s, vv.x); upd(m, s, vv.y); upd(m, s, vv.z); upd(m, s, vv.w);
    }
    for (int j = n4 + tid; j < n; j += 256) upd(m, s, row[j]);

    #pragma unroll
    for (int o = 16; o > 0; o >>= 1) {
        float mo = __shfl_xor_sync(0xffffffffu, m, o);
        float so = __shfl_xor_sync(0xffffffffu, s, o);
        float M  = fmaxf(m, mo);
        s = s * __expf((m - M) * scale) + so * __expf((mo - M) * scale);
        m = M;
    }
    if (lane == 0) { shm[wid] = m; shs[wid] = s; }
    __syncthreads();
    float M = shm[0], Sm = shs[0];
    #pragma unroll
    for (int t = 1; t < 8; t++) {
        float mo = shm[t], so = shs[t];
        float Mx = fmaxf(M, mo);
        Sm = Sm * __expf((M - Mx) * scale) + so * __expf((mo - Mx) * scale);
        M = Mx;
    }
    const float inv = 1.0f / Sm;

    for (int j = tid * 4; j < n4; j += 1024) {
        float4 vv = *(const float4*)(row + j);
        vv.x = __expf((vv.x - M) * scale) * inv;
        vv.y = __expf((vv.y - M) * scale) * inv;
        vv.z = __expf((vv.z - M) * scale) * inv;
        vv.w = __expf((vv.w - M) * scale) * inv;
        *(float4*)(row + j) = vv;
    }
    for (int j = n4 + tid; j < n; j += 256)
        row[j] = __expf((row[j] - M) * scale) * inv;

    // zero-fill to the edge of this row's diagonal 256-block (PV reads
    // whole 256-row K blocks under KLIM)
    const int end = ((i >> 8) + 1) << 8;
    for (int j = n + tid; j < end; j += 256) row[j] = 0.f;
}

// ---------------------------------------------------------------------------
extern "C" void kernel_launch(void* const* d_in, const int* in_sizes, int n_in,
                              void* d_out, int out_size)
{
    const float* x  = (const float*)d_in[0];
    const float* Wq = (const float*)d_in[1];
    const float* Wk = (const float*)d_in[2];
    const float* Wv = (const float*)d_in[3];
    float* out = (float*)d_out;

    static float *q = nullptr, *k = nullptr, *v = nullptr, *vt = nullptr,
                 *wt = nullptr, *sc = nullptr;
    static bool init = false;
    if (!init) {
        cudaGetSymbolAddress((void**)&q,  g_q);
        cudaGetSymbolAddress((void**)&k,  g_k);
        cudaGetSymbolAddress((void**)&v,  g_v);
        cudaGetSymbolAddress((void**)&vt, g_vt);
        cudaGetSymbolAddress((void**)&wt, g_wt);
        cudaGetSymbolAddress((void**)&sc, g_s);
        cudaFuncSetAttribute(k_qkv,
                             cudaFuncAttributeMaxDynamicSharedMemorySize, SMEM_BYTES);
        cudaFuncSetAttribute(k_scores,
                             cudaFuncAttributeMaxDynamicSharedMemorySize, SMEM_BYTES);
        cudaFuncSetAttribute(k_pv,
                             cudaFuncAttributeMaxDynamicSharedMemorySize, SMEM_BYTES);
        init = true;
    }

    // 1) W^T (B operand is [N,K] = [d_out][d_in])
    k_wt<<<dim3(D / 32, D / 32, 3), 256>>>(Wq, Wk, Wv, wt);

    // 2) QKV projections
    k_qkv<<<dim3(D / BN, (Bb * S) / BM, 3), 256, SMEM_BYTES>>>(x, wt, q, k, v);

    // 3) V^T for PV
    k_vt<<<dim3(S / 32, D / 32, Bb), 256>>>(v, vt);

    // 4) scores = Q K^T  (K's natural [S,D] layout is the [N,K] operand)
    k_scores<<<dim3(S / BN, S / BM, Bb), 256, SMEM_BYTES>>>(q, k, sc);

    // 5) softmax
    softmax_causal<<<Bb * S, 256>>>(sc);

    // 6) out = P V  (B = V^T)
    k_pv<<<dim3(D / BN, S / BM, Bb), 256, SMEM_BYTES>>>(sc, vt, out);
}

// round 14
// speedup vs baseline: 1.4843x; 1.1563x over previous
#include <cuda_runtime.h>
#include <cstdint>

// ============================================================================
// CausalAttention, B=4, S=4096, D=1024, fp32 in/out.
// R13: all GEMM operands pre-split into hi/lo bf16 arrays in gmem.
// GEMM mainloop: cp.async.cg 16B gmem->swizzled smem (3-stage pipeline,
// no cvt/LDG/STS in loop), ldmatrix.x4 fragments, bf16x3 mma.sync m16n8k16.
// Block tile 128x128x32, 4x2 warps of 32x64 (best measured config, R8).
// QKV + softmax epilogues emit hi/lo bf16 directly.
// ============================================================================

static constexpr int Bb = 4;
static constexpr int S  = 4096;
static constexpr int D  = 1024;
static constexpr int BM = 128;
static constexpr int BN = 128;
static constexpr int BK = 32;                 // K elems per chunk (16 words)

static constexpr int TILE_W      = 2048;      // words per [128][16] tile (8 KB)
static constexpr int STAGE_W     = 4 * TILE_W;            // Ah,Al,Bh,Bl
static constexpr int STAGE_BYTES = STAGE_W * 4;           // 32 KB
static constexpr int NSTAGE      = 3;
static constexpr int SMEM_BYTES  = NSTAGE * STAGE_BYTES;  // 98304

// gmem scratch (hi/lo bf16 stored as u32 words = 2 elems; fp32 scores)
static __device__ uint32_t g_xh [(size_t)Bb * S * D / 2];
static __device__ uint32_t g_xl [(size_t)Bb * S * D / 2];
static __device__ uint32_t g_wth[(size_t)3 * D * D / 2];
static __device__ uint32_t g_wtl[(size_t)3 * D * D / 2];
static __device__ uint32_t g_qh [(size_t)Bb * S * D / 2];
static __device__ uint32_t g_ql [(size_t)Bb * S * D / 2];
static __device__ uint32_t g_kh [(size_t)Bb * S * D / 2];
static __device__ uint32_t g_kl [(size_t)Bb * S * D / 2];
static __device__ uint32_t g_vh [(size_t)Bb * S * D / 2];
static __device__ uint32_t g_vl [(size_t)Bb * S * D / 2];
static __device__ uint32_t g_vth[(size_t)Bb * D * S / 2];
static __device__ uint32_t g_vtl[(size_t)Bb * D * S / 2];
static __device__ float    g_s  [(size_t)Bb * S * S];
static __device__ uint32_t g_ph [(size_t)Bb * S * S / 2];
static __device__ uint32_t g_pl [(size_t)Bb * S * S / 2];

// ---------------------------------------------------------------------------
__device__ __forceinline__ uint32_t tile_addr(uint32_t row, uint32_t w) {
    const uint32_t line = row >> 1;
    const uint32_t off  = ((row & 1u) << 4) + w;
    return line * 32u + (off ^ ((line & 7u) << 2));
}
__device__ __forceinline__ uint32_t smem_u32(const void* p) {
    uint32_t a;
    asm("{ .reg .u64 t; cvta.to.shared.u64 t, %1; cvt.u32.u64 %0, t; }"
        : "=r"(a) : "l"(p));
    return a;
}
__device__ __forceinline__ void ldsm_x4(uint32_t (&r)[4], uint32_t saddr) {
    asm volatile("ldmatrix.sync.aligned.m8n8.x4.shared.b16 {%0,%1,%2,%3}, [%4];"
                 : "=r"(r[0]), "=r"(r[1]), "=r"(r[2]), "=r"(r[3])
                 : "r"(saddr));
}
__device__ __forceinline__ void cp16(uint32_t dst, const void* src) {
    asm volatile("cp.async.cg.shared.global [%0], [%1], 16;"
                 :: "r"(dst), "l"(src));
}
__device__ __forceinline__ void cp_commit() {
    asm volatile("cp.async.commit_group;" ::: "memory");
}
template<int NN>
__device__ __forceinline__ void cp_wait() {
    asm volatile("cp.async.wait_group %0;" :: "n"(NN) : "memory");
}
// split (x0, x1) into hi/lo bf16x2 words (lower 16 bits = x0)
__device__ __forceinline__ void bf16_split2(float x0, float x1,
                                            uint32_t& hw, uint32_t& lw) {
    asm("cvt.rn.bf16x2.f32 %0, %1, %2;" : "=r"(hw) : "f"(x1), "f"(x0));
    const float h0 = __uint_as_float(hw << 16);
    const float h1 = __uint_as_float(hw & 0xffff0000u);
    const float r0 = x0 - h0;
    const float r1 = x1 - h1;
    asm("cvt.rn.bf16x2.f32 %0, %1, %2;" : "=r"(lw) : "f"(r1), "f"(r0));
}
__device__ __forceinline__ void mma_bf16(float (&d)[4], const uint32_t (&a)[4],
                                         uint32_t b0, uint32_t b1) {
    asm("mma.sync.aligned.m16n8k16.row.col.f32.bf16.bf16.f32 "
        "{%0,%1,%2,%3}, {%4,%5,%6,%7}, {%8,%9}, {%0,%1,%2,%3};"
        : "+f"(d[0]), "+f"(d[1]), "+f"(d[2]), "+f"(d[3])
        : "r"(a[0]), "r"(a[1]), "r"(a[2]), "r"(a[3]), "r"(b0), "r"(b1));
}

// ---------------------------------------------------------------------------
// C[bm,bn tile] = A * B^T; A,B given as hi/lo bf16 element arrays
// (A: [M][K] lda, B: [N][K] ldb). SPLIT_OUT: write hi/lo bf16 words to Ch/Cl
// instead of fp32 C. KLIM: K limited to (bm+1)*BM.
// ---------------------------------------------------------------------------
template<bool KLIM, bool SPLIT_OUT>
__device__ __forceinline__ void
gemm_core(const uint16_t* __restrict__ Ah, const uint16_t* __restrict__ Al,
          const uint16_t* __restrict__ Bh, const uint16_t* __restrict__ Bl,
          float* __restrict__ C, uint32_t* __restrict__ Ch,
          uint32_t* __restrict__ Cl,
          int N, int K, int lda, int ldb, int bm, int bn)
{
    const int kEnd   = KLIM ? min(K, (bm + 1) * BM) : K;
    const int nchunk = kEnd / BK;

    extern __shared__ uint32_t sm[];
    const uint32_t smb = smem_u32(sm);

    const int tid  = threadIdx.x;
    const int wid  = tid >> 5;
    const int wm   = wid & 3;               // 4 warps along M
    const int wn   = wid >> 2;              // 2 warps along N
    const int lane = tid & 31;
    const int g    = lane >> 2;
    const int c    = lane & 3;
    const int l8   = lane & 7;
    const int lm   = lane >> 3;

    uint32_t relA[2][2], relB0[2];
    #pragma unroll
    for (int mi = 0; mi < 2; mi++) {
        const uint32_t row = wm * 32 + mi * 16 + ((lm & 1) << 3) + l8;
        const uint32_t w   = (lm >> 1) << 2;
        relA[mi][0] = tile_addr(row, w) * 4u;
        relA[mi][1] = tile_addr(row, w + 8) * 4u;
    }
    {
        const uint32_t row = wn * 64 + ((lm >> 1) << 3) + l8;
        const uint32_t w   = (lm & 1) << 2;
        relB0[0] = tile_addr(row, w) * 4u;
        relB0[1] = tile_addr(row, w + 8) * 4u;
    }

    // staging map: thread t -> row t>>1, half h = t&1 (16 elems = 2 x 16B)
    const int row = tid >> 1;
    const int h   = tid & 1;
    const uint32_t d0 = tile_addr(row, h * 8) * 4u;
    const uint32_t d1 = (tile_addr(row, h * 8) ^ 4u) * 4u;
    const uint16_t* sAh = Ah + (size_t)(bm * BM + row) * lda + h * 16;
    const uint16_t* sAl = Al + (size_t)(bm * BM + row) * lda + h * 16;
    const uint16_t* sBh = Bh + (size_t)(bn * BN + row) * ldb + h * 16;
    const uint16_t* sBl = Bl + (size_t)(bn * BN + row) * ldb + h * 16;

    auto issue_stage = [&](int sidx, int kc) {
        const uint32_t b = smb + sidx * STAGE_BYTES;
        cp16(b + d0,                     sAh + kc);
        cp16(b + d1,                     sAh + kc + 8);
        cp16(b + STAGE_BYTES / 4 + d0,   sAl + kc);        // +8192 B
        cp16(b + STAGE_BYTES / 4 + d1,   sAl + kc + 8);
        cp16(b + STAGE_BYTES / 2 + d0,   sBh + kc);        // +16384 B
        cp16(b + STAGE_BYTES / 2 + d1,   sBh + kc + 8);
        cp16(b + 3 * STAGE_BYTES / 4 + d0, sBl + kc);      // +24576 B
        cp16(b + 3 * STAGE_BYTES / 4 + d1, sBl + kc + 8);
    };

    // prologue: 2 chunks in flight
    issue_stage(0, 0);
    cp_commit();
    if (nchunk > 1) issue_stage(1, BK);
    cp_commit();

    float acc[2][8][4];
    #pragma unroll
    for (int mi = 0; mi < 2; mi++)
        #pragma unroll
        for (int ni = 0; ni < 8; ni++)
            #pragma unroll
            for (int q = 0; q < 4; q++) acc[mi][ni][q] = 0.f;

    int sidx = 0;
    for (int ic = 0; ic < nchunk; ic++) {
        cp_wait<1>();                       // group ic complete
        __syncthreads();

        // issue chunk ic+2 into the stage freed in iteration ic-1
        if (ic + 2 < nchunk) {
            int ns = sidx + 2;
            if (ns >= NSTAGE) ns -= NSTAGE;
            issue_stage(ns, (ic + 2) * BK);
        }
        cp_commit();                        // one group per iteration, always

        const uint32_t base = smb + sidx * STAGE_BYTES;
        const uint32_t bAh = base;
        const uint32_t bAl = base + STAGE_BYTES / 4;
        const uint32_t bBh = base + STAGE_BYTES / 2;
        const uint32_t bBl = base + 3 * STAGE_BYTES / 4;

        #pragma unroll
        for (int kt = 0; kt < 2; kt++) {
            uint32_t ah[2][4], al[2][4], bh[4][4], bl[4][4];
            #pragma unroll
            for (int mi = 0; mi < 2; mi++) {
                ldsm_x4(ah[mi], bAh + relA[mi][kt]);
                ldsm_x4(al[mi], bAl + relA[mi][kt]);
            }
            #pragma unroll
            for (int p = 0; p < 4; p++) {
                ldsm_x4(bh[p], bBh + relB0[kt] + p * 1024u);
                ldsm_x4(bl[p], bBl + relB0[kt] + p * 1024u);
            }
            #pragma unroll
            for (int mi = 0; mi < 2; mi++)
                #pragma unroll
                for (int ni = 0; ni < 8; ni++)
                    mma_bf16(acc[mi][ni], ah[mi],
                             bh[ni >> 1][(ni & 1) * 2],
                             bh[ni >> 1][(ni & 1) * 2 + 1]);
            #pragma unroll
            for (int mi = 0; mi < 2; mi++)
                #pragma unroll
                for (int ni = 0; ni < 8; ni++)
                    mma_bf16(acc[mi][ni], al[mi],
                             bh[ni >> 1][(ni & 1) * 2],
                             bh[ni >> 1][(ni & 1) * 2 + 1]);
            #pragma unroll
            for (int mi = 0; mi < 2; mi++)
                #pragma unroll
                for (int ni = 0; ni < 8; ni++)
                    mma_bf16(acc[mi][ni], ah[mi],
                             bl[ni >> 1][(ni & 1) * 2],
                             bl[ni >> 1][(ni & 1) * 2 + 1]);
        }

        __syncthreads();                    // readers done before stage reuse
        if (++sidx == NSTAGE) sidx = 0;
    }

    // epilogue
    #pragma unroll
    for (int mi = 0; mi < 2; mi++) {
        const int r0 = bm * BM + wm * 32 + mi * 16 + g;
        #pragma unroll
        for (int ni = 0; ni < 8; ni++) {
            const int cc = bn * BN + wn * 64 + ni * 8 + c * 2;
            if (SPLIT_OUT) {
                uint32_t hw, lw;
                bf16_split2(acc[mi][ni][0], acc[mi][ni][1], hw, lw);
                Ch[((size_t)r0 * N + cc) >> 1] = hw;
                Cl[((size_t)r0 * N + cc) >> 1] = lw;
                bf16_split2(acc[mi][ni][2], acc[mi][ni][3], hw, lw);
                Ch[((size_t)(r0 + 8) * N + cc) >> 1] = hw;
                Cl[((size_t)(r0 + 8) * N + cc) >> 1] = lw;
            } else {
                float2 v0 = make_float2(acc[mi][ni][0], acc[mi][ni][1]);
                float2 v1 = make_float2(acc[mi][ni][2], acc[mi][ni][3]);
                *(float2*)(C + (size_t)r0 * N + cc)       = v0;
                *(float2*)(C + (size_t)(r0 + 8) * N + cc) = v1;
            }
        }
    }
}

// ---- GEMM kernels ----------------------------------------------------------
__global__ void __launch_bounds__(256, 1)
k_qkv()
{
    const size_t z = blockIdx.z;
    const uint16_t* wh = (const uint16_t*)g_wth + z * D * D;
    const uint16_t* wl = (const uint16_t*)g_wtl + z * D * D;
    uint32_t* oh = z == 0 ? g_qh : (z == 1 ? g_kh : g_vh);
    uint32_t* ol = z == 0 ? g_ql : (z == 1 ? g_kl : g_vl);
    gemm_core<false, true>((const uint16_t*)g_xh, (const uint16_t*)g_xl,
                           wh, wl, nullptr, oh, ol,
                           D, D, D, D, blockIdx.y, blockIdx.x);
}

__global__ void __launch_bounds__(256, 1)
k_scores()
{
    const int bm = blockIdx.y, bn = blockIdx.x;
    if (bn > bm) return;
    const size_t z = blockIdx.z;
    gemm_core<false, false>((const uint16_t*)g_qh + z * S * D,
                            (const uint16_t*)g_ql + z * S * D,
                            (const uint16_t*)g_kh + z * S * D,
                            (const uint16_t*)g_kl + z * S * D,
                            g_s + z * S * S, nullptr, nullptr,
                            S, D, D, D, bm, bn);
}

__global__ void __launch_bounds__(256, 1)
k_pv(float* __restrict__ out)
{
    const size_t z = blockIdx.z;
    gemm_core<true, false>((const uint16_t*)g_ph + z * S * S,
                           (const uint16_t*)g_pl + z * S * S,
                           (const uint16_t*)g_vth + z * D * S,
                           (const uint16_t*)g_vtl + z * D * S,
                           out + z * S * D, nullptr, nullptr,
                           D, S, S, S, blockIdx.y, blockIdx.x);
}

// ---- prep kernels ----------------------------------------------------------
// split x: fp32 -> hi/lo bf16 words
__global__ void __launch_bounds__(256)
k_split_x(const float* __restrict__ x)
{
    const size_t n4 = (size_t)Bb * S * D / 4;
    for (size_t i = blockIdx.x * 256 + threadIdx.x; i < n4;
         i += (size_t)gridDim.x * 256) {
        float4 f = *(const float4*)(x + i * 4);
        uint32_t h0, l0, h1, l1;
        bf16_split2(f.x, f.y, h0, l0);
        bf16_split2(f.z, f.w, h1, l1);
        g_xh[i * 2] = h0;  g_xh[i * 2 + 1] = h1;
        g_xl[i * 2] = l0;  g_xl[i * 2 + 1] = l1;
    }
}

// W -> transposed split: wt[z][d_out][d_in]
__global__ void __launch_bounds__(256)
k_wt(const float* __restrict__ wq, const float* __restrict__ wk,
     const float* __restrict__ wv)
{
    __shared__ float t[32][33];
    const float* src = blockIdx.z == 0 ? wq : (blockIdx.z == 1 ? wk : wv);
    uint16_t* dh = (uint16_t*)g_wth + (size_t)blockIdx.z * D * D;
    uint16_t* dl = (uint16_t*)g_wtl + (size_t)blockIdx.z * D * D;
    const int r0 = blockIdx.x << 5, c0 = blockIdx.y << 5;
    const int tx = threadIdx.x & 31, ty = threadIdx.x >> 5;
    #pragma unroll
    for (int i = 0; i < 32; i += 8)
        t[ty + i][tx] = src[(size_t)(r0 + ty + i) * D + c0 + tx];
    __syncthreads();
    #pragma unroll
    for (int i = 0; i < 32; i += 8) {
        float v = t[tx][ty + i];
        uint32_t hw, lw;
        bf16_split2(v, 0.f, hw, lw);
        const size_t idx = (size_t)(c0 + ty + i) * D + r0 + tx;
        dh[idx] = (uint16_t)hw;
        dl[idx] = (uint16_t)lw;
    }
}

// transpose split v: [S][D] -> [D][S] (both hi and lo, bf16)
__global__ void __launch_bounds__(256)
k_vt()
{
    __shared__ uint16_t th[32][34], tl[32][34];
    const uint16_t* sh = (const uint16_t*)g_vh + (size_t)blockIdx.z * S * D;
    const uint16_t* sl = (const uint16_t*)g_vl + (size_t)blockIdx.z * S * D;
    uint16_t* dh = (uint16_t*)g_vth + (size_t)blockIdx.z * D * S;
    uint16_t* dl = (uint16_t*)g_vtl + (size_t)blockIdx.z * D * S;
    const int s0 = blockIdx.x << 5, d0 = blockIdx.y << 5;
    const int tx = threadIdx.x & 31, ty = threadIdx.x >> 5;
    #pragma unroll
    for (int i = 0; i < 32; i += 8) {
        th[ty + i][tx] = sh[(size_t)(s0 + ty + i) * D + d0 + tx];
        tl[ty + i][tx] = sl[(size_t)(s0 + ty + i) * D + d0 + tx];
    }
    __syncthreads();
    #pragma unroll
    for (int i = 0; i < 32; i += 8) {
        const size_t idx = (size_t)(d0 + ty + i) * S + s0 + tx;
        dh[idx] = th[tx][ty + i];
        dl[idx] = tl[tx][ty + i];
    }
}

// ---- softmax: reads fp32 scores, writes hi/lo bf16 probabilities -----------
__global__ void __launch_bounds__(256)
softmax_causal()
{
    const int r = blockIdx.x;
    const int b = r >> 12;
    const int i = r & (S - 1);
    const float* row = g_s + ((size_t)b * S * S) + ((size_t)i * S);
    uint32_t* ph = g_ph + (((size_t)b * S * S) + ((size_t)i * S)) / 2;
    uint32_t* pl = g_pl + (((size_t)b * S * S) + ((size_t)i * S)) / 2;
    const int n  = i + 1;
    const int n4 = n & ~3;
    const int tid  = threadIdx.x;
    const int wid  = tid >> 5;
    const int lane = tid & 31;
    const float scale = 0.03125f;   // 1/sqrt(1024)

    __shared__ float shm[8], shs[8];

    auto upd = [&](float& m, float& s, float v) {
        if (v <= m) s += __expf((v - m) * scale);
        else { s = s * __expf((m - v) * scale) + 1.f; m = v; }
    };

    float m = -3.0e38f, s = 0.f;
    for (int j = tid * 4; j < n4; j += 1024) {
        float4 vv = *(const float4*)(row + j);
        upd(m, s, vv.x); upd(m, s, vv.y); upd(m, s, vv.z); upd(m, s, vv.w);
    }
    for (int j = n4 + tid; j < n; j += 256) upd(m, s, row[j]);

    #pragma unroll
    for (int o = 16; o > 0; o >>= 1) {
        float mo = __shfl_xor_sync(0xffffffffu, m, o);
        float so = __shfl_xor_sync(0xffffffffu, s, o);
        float M  = fmaxf(m, mo);
        s = s * __expf((m - M) * scale) + so * __expf((mo - M) * scale);
        m = M;
    }
    if (lane == 0) { shm[wid] = m; shs[wid] = s; }
    __syncthreads();
    float M = shm[0], Sm = shs[0];
    #pragma unroll
    for (int t = 1; t < 8; t++) {
        float mo = shm[t], so = shs[t];
        float Mx = fmaxf(M, mo);
        Sm = Sm * __expf((M - Mx) * scale) + so * __expf((mo - Mx) * scale);
        M = Mx;
    }
    const float inv = 1.0f / Sm;

    // write probabilities (hi/lo bf16), zero-filled to diagonal 128-block edge
    const int end = ((i >> 7) + 1) << 7;
    for (int j = tid * 2; j < end; j += 512) {
        float e0 = (j     < n) ? __expf((row[j]     - M) * scale) * inv : 0.f;
        float e1 = (j + 1 < n) ? __expf((row[j + 1] - M) * scale) * inv : 0.f;
        uint32_t hw, lw;
        bf16_split2(e0, e1, hw, lw);
        ph[j >> 1] = hw;
        pl[j >> 1] = lw;
    }
}

// ---------------------------------------------------------------------------
extern "C" void kernel_launch(void* const* d_in, const int* in_sizes, int n_in,
                              void* d_out, int out_size)
{
    const float* x  = (const float*)d_in[0];
    const float* Wq = (const float*)d_in[1];
    const float* Wk = (const float*)d_in[2];
    const float* Wv = (const float*)d_in[3];
    float* out = (float*)d_out;

    static bool init = false;
    if (!init) {
        cudaFuncSetAttribute(k_qkv,
                             cudaFuncAttributeMaxDynamicSharedMemorySize, SMEM_BYTES);
        cudaFuncSetAttribute(k_scores,
                             cudaFuncAttributeMaxDynamicSharedMemorySize, SMEM_BYTES);
        cudaFuncSetAttribute(k_pv,
                             cudaFuncAttributeMaxDynamicSharedMemorySize, SMEM_BYTES);
        init = true;
    }

    // 1) split inputs into hi/lo bf16
    k_split_x<<<2048, 256>>>(x);
    k_wt<<<dim3(D / 32, D / 32, 3), 256>>>(Wq, Wk, Wv);

    // 2) QKV projections (emit hi/lo bf16 q,k,v directly)
    k_qkv<<<dim3(D / BN, (Bb * S) / BM, 3), 256, SMEM_BYTES>>>();

    // 3) V^T (split)
    k_vt<<<dim3(S / 32, D / 32, Bb), 256>>>();

    // 4) scores = Q K^T (fp32 out, causal block skip)
    k_scores<<<dim3(S / BN, S / BM, Bb), 256, SMEM_BYTES>>>();

    // 5) softmax -> hi/lo bf16 P
    softmax_causal<<<Bb * S, 256>>>();

    // 6) out = P V
    k_pv<<<dim3(D / BN, S / BM, Bb), 256, SMEM_BYTES>>>(out);
}

// round 15
// speedup vs baseline: 1.6245x; 1.0944x over previous
#include <cuda_runtime.h>
#include <cstdint>

// ============================================================================
// CausalAttention, B=4, S=4096, D=1024, fp32 in/out.
// R15: R13 (pre-split hi/lo bf16 operands in gmem + cp.async 3-stage pipeline,
// ldmatrix.x4, bf16x3 mma.sync) with a register-lean consumer so TWO CTAs fit
// per SM (__launch_bounds__(256,2)) — the co-resident CTA fills each chunk's
// serial-skeleton bubbles; cp.async staging is register-free so 2 CTAs do not
// double crossbar pressure the way R11's LDG/cvt/STS staging did.
// ============================================================================

static constexpr int Bb = 4;
static constexpr int S  = 4096;
static constexpr int D  = 1024;
static constexpr int BM = 128;
static constexpr int BN = 128;
static constexpr int BK = 32;                 // K elems per chunk (16 words)

static constexpr int STAGE_BYTES = 32768;     // Ah,Al,Bh,Bl tiles (8 KB each)
static constexpr int NSTAGE      = 3;
static constexpr int SMEM_BYTES  = NSTAGE * STAGE_BYTES;  // 98304

// gmem scratch (hi/lo bf16 stored as u32 words = 2 elems; fp32 scores)
static __device__ uint32_t g_xh [(size_t)Bb * S * D / 2];
static __device__ uint32_t g_xl [(size_t)Bb * S * D / 2];
static __device__ uint32_t g_wth[(size_t)3 * D * D / 2];
static __device__ uint32_t g_wtl[(size_t)3 * D * D / 2];
static __device__ uint32_t g_qh [(size_t)Bb * S * D / 2];
static __device__ uint32_t g_ql [(size_t)Bb * S * D / 2];
static __device__ uint32_t g_kh [(size_t)Bb * S * D / 2];
static __device__ uint32_t g_kl [(size_t)Bb * S * D / 2];
static __device__ uint32_t g_vh [(size_t)Bb * S * D / 2];
static __device__ uint32_t g_vl [(size_t)Bb * S * D / 2];
static __device__ uint32_t g_vth[(size_t)Bb * D * S / 2];
static __device__ uint32_t g_vtl[(size_t)Bb * D * S / 2];
static __device__ float    g_s  [(size_t)Bb * S * S];
static __device__ uint32_t g_ph [(size_t)Bb * S * S / 2];
static __device__ uint32_t g_pl [(size_t)Bb * S * S / 2];

// ---------------------------------------------------------------------------
__device__ __forceinline__ uint32_t tile_addr(uint32_t row, uint32_t w) {
    const uint32_t line = row >> 1;
    const uint32_t off  = ((row & 1u) << 4) + w;
    return line * 32u + (off ^ ((line & 7u) << 2));
}
__device__ __forceinline__ uint32_t smem_u32(const void* p) {
    uint32_t a;
    asm("{ .reg .u64 t; cvta.to.shared.u64 t, %1; cvt.u32.u64 %0, t; }"
        : "=r"(a) : "l"(p));
    return a;
}
__device__ __forceinline__ void ldsm_x4(uint32_t (&r)[4], uint32_t saddr) {
    asm volatile("ldmatrix.sync.aligned.m8n8.x4.shared.b16 {%0,%1,%2,%3}, [%4];"
                 : "=r"(r[0]), "=r"(r[1]), "=r"(r[2]), "=r"(r[3])
                 : "r"(saddr));
}
__device__ __forceinline__ void cp16(uint32_t dst, const void* src) {
    asm volatile("cp.async.cg.shared.global [%0], [%1], 16;"
                 :: "r"(dst), "l"(src));
}
__device__ __forceinline__ void cp_commit() {
    asm volatile("cp.async.commit_group;" ::: "memory");
}
template<int NN>
__device__ __forceinline__ void cp_wait() {
    asm volatile("cp.async.wait_group %0;" :: "n"(NN) : "memory");
}
// split (x0, x1) into hi/lo bf16x2 words (lower 16 bits = x0)
__device__ __forceinline__ void bf16_split2(float x0, float x1,
                                            uint32_t& hw, uint32_t& lw) {
    asm("cvt.rn.bf16x2.f32 %0, %1, %2;" : "=r"(hw) : "f"(x1), "f"(x0));
    const float h0 = __uint_as_float(hw << 16);
    const float h1 = __uint_as_float(hw & 0xffff0000u);
    const float r0 = x0 - h0;
    const float r1 = x1 - h1;
    asm("cvt.rn.bf16x2.f32 %0, %1, %2;" : "=r"(lw) : "f"(r1), "f"(r0));
}
__device__ __forceinline__ void mma_bf16(float (&d)[4], const uint32_t (&a)[4],
                                         uint32_t b0, uint32_t b1) {
    asm("mma.sync.aligned.m16n8k16.row.col.f32.bf16.bf16.f32 "
        "{%0,%1,%2,%3}, {%4,%5,%6,%7}, {%8,%9}, {%0,%1,%2,%3};"
        : "+f"(d[0]), "+f"(d[1]), "+f"(d[2]), "+f"(d[3])
        : "r"(a[0]), "r"(a[1]), "r"(a[2]), "r"(a[3]), "r"(b0), "r"(b1));
}

// ---------------------------------------------------------------------------
// C[bm,bn tile] = A * B^T; A,B are hi/lo bf16 element arrays (A: [M][K] lda,
// B: [N][K] ldb). SPLIT_OUT: write hi/lo bf16 words to Ch/Cl. KLIM: K limited
// to (bm+1)*BM. 256 threads, register-lean (2 CTAs/SM).
// ---------------------------------------------------------------------------
template<bool KLIM, bool SPLIT_OUT>
__device__ __forceinline__ void
gemm_core(const uint16_t* __restrict__ Ah, const uint16_t* __restrict__ Al,
          const uint16_t* __restrict__ Bh, const uint16_t* __restrict__ Bl,
          float* __restrict__ C, uint32_t* __restrict__ Ch,
          uint32_t* __restrict__ Cl,
          int N, int K, int lda, int ldb, int bm, int bn)
{
    const int kEnd   = KLIM ? min(K, (bm + 1) * BM) : K;
    const int nchunk = kEnd / BK;

    extern __shared__ uint32_t sm[];
    const uint32_t smb = smem_u32(sm);

    const int tid  = threadIdx.x;
    const int wid  = tid >> 5;
    const int wm   = wid & 3;               // 4 warps along M
    const int wn   = wid >> 2;              // 2 warps along N
    const int lane = tid & 31;
    const int g    = lane >> 2;
    const int c    = lane & 3;
    const int l8   = lane & 7;
    const int lm   = lane >> 3;

    uint32_t relA[2][2], relB0[2];
    #pragma unroll
    for (int mi = 0; mi < 2; mi++) {
        const uint32_t row = wm * 32 + mi * 16 + ((lm & 1) << 3) + l8;
        const uint32_t w   = (lm >> 1) << 2;
        relA[mi][0] = tile_addr(row, w) * 4u;
        relA[mi][1] = tile_addr(row, w + 8) * 4u;
    }
    {
        const uint32_t row = wn * 64 + ((lm >> 1) << 3) + l8;
        const uint32_t w   = (lm & 1) << 2;
        relB0[0] = tile_addr(row, w) * 4u;
        relB0[1] = tile_addr(row, w + 8) * 4u;
    }

    // staging map: thread t -> row t>>1, half h = t&1 (16 elems = 2 x 16B)
    const int row = tid >> 1;
    const int h   = tid & 1;
    const uint32_t d0 = tile_addr(row, h * 8) * 4u;
    const uint32_t d1 = (tile_addr(row, h * 8) ^ 4u) * 4u;
    const uint16_t* sAh = Ah + (size_t)(bm * BM + row) * lda + h * 16;
    const uint16_t* sAl = Al + (size_t)(bm * BM + row) * lda + h * 16;
    const uint16_t* sBh = Bh + (size_t)(bn * BN + row) * ldb + h * 16;
    const uint16_t* sBl = Bl + (size_t)(bn * BN + row) * ldb + h * 16;

    auto issue_stage = [&](int sidx, int kc) {
        const uint32_t b = smb + sidx * STAGE_BYTES;
        cp16(b + d0,                       sAh + kc);
        cp16(b + d1,                       sAh + kc + 8);
        cp16(b + STAGE_BYTES / 4 + d0,     sAl + kc);       // +8192 B
        cp16(b + STAGE_BYTES / 4 + d1,     sAl + kc + 8);
        cp16(b + STAGE_BYTES / 2 + d0,     sBh + kc);       // +16384 B
        cp16(b + STAGE_BYTES / 2 + d1,     sBh + kc + 8);
        cp16(b + 3 * STAGE_BYTES / 4 + d0, sBl + kc);       // +24576 B
        cp16(b + 3 * STAGE_BYTES / 4 + d1, sBl + kc + 8);
    };

    // prologue: 2 chunks in flight
    issue_stage(0, 0);
    cp_commit();
    if (nchunk > 1) issue_stage(1, BK);
    cp_commit();

    float acc[2][8][4];
    #pragma unroll
    for (int mi = 0; mi < 2; mi++)
        #pragma unroll
        for (int ni = 0; ni < 8; ni++)
            #pragma unroll
            for (int q = 0; q < 4; q++) acc[mi][ni][q] = 0.f;

    int sidx = 0;
    for (int ic = 0; ic < nchunk; ic++) {
        cp_wait<1>();                       // group ic complete
        __syncthreads();

        // issue chunk ic+2 into the stage freed in iteration ic-1
        if (ic + 2 < nchunk) {
            int ns = sidx + 2;
            if (ns >= NSTAGE) ns -= NSTAGE;
            issue_stage(ns, (ic + 2) * BK);
        }
        cp_commit();                        // one group per iteration, always

        const uint32_t base = smb + sidx * STAGE_BYTES;
        const uint32_t bAh = base;
        const uint32_t bAl = base + STAGE_BYTES / 4;
        const uint32_t bBh = base + STAGE_BYTES / 2;
        const uint32_t bBl = base + 3 * STAGE_BYTES / 4;

        #pragma unroll
        for (int kt = 0; kt < 2; kt++) {
            uint32_t ah[2][4], al[2][4];
            #pragma unroll
            for (int mi = 0; mi < 2; mi++) {
                ldsm_x4(ah[mi], bAh + relA[mi][kt]);
                ldsm_x4(al[mi], bAl + relA[mi][kt]);
            }
            #pragma unroll
            for (int p = 0; p < 4; p++) {
                uint32_t bh[4], bl[4];
                ldsm_x4(bh, bBh + relB0[kt] + p * 1024u);
                ldsm_x4(bl, bBl + relB0[kt] + p * 1024u);
                const int n0 = 2 * p, n1 = 2 * p + 1;
                // grouped by split term; 4 distinct accumulators per group
                mma_bf16(acc[0][n0], ah[0], bh[0], bh[1]);
                mma_bf16(acc[0][n1], ah[0], bh[2], bh[3]);
                mma_bf16(acc[1][n0], ah[1], bh[0], bh[1]);
                mma_bf16(acc[1][n1], ah[1], bh[2], bh[3]);
                mma_bf16(acc[0][n0], al[0], bh[0], bh[1]);
                mma_bf16(acc[0][n1], al[0], bh[2], bh[3]);
                mma_bf16(acc[1][n0], al[1], bh[0], bh[1]);
                mma_bf16(acc[1][n1], al[1], bh[2], bh[3]);
                mma_bf16(acc[0][n0], ah[0], bl[0], bl[1]);
                mma_bf16(acc[0][n1], ah[0], bl[2], bl[3]);
                mma_bf16(acc[1][n0], ah[1], bl[0], bl[1]);
                mma_bf16(acc[1][n1], ah[1], bl[2], bl[3]);
            }
        }

        __syncthreads();                    // readers done before stage reuse
        if (++sidx == NSTAGE) sidx = 0;
    }

    // epilogue
    #pragma unroll
    for (int mi = 0; mi < 2; mi++) {
        const int r0 = bm * BM + wm * 32 + mi * 16 + g;
        #pragma unroll
        for (int ni = 0; ni < 8; ni++) {
            const int cc = bn * BN + wn * 64 + ni * 8 + c * 2;
            if (SPLIT_OUT) {
                uint32_t hw, lw;
                bf16_split2(acc[mi][ni][0], acc[mi][ni][1], hw, lw);
                Ch[((size_t)r0 * N + cc) >> 1] = hw;
                Cl[((size_t)r0 * N + cc) >> 1] = lw;
                bf16_split2(acc[mi][ni][2], acc[mi][ni][3], hw, lw);
                Ch[((size_t)(r0 + 8) * N + cc) >> 1] = hw;
                Cl[((size_t)(r0 + 8) * N + cc) >> 1] = lw;
            } else {
                float2 v0 = make_float2(acc[mi][ni][0], acc[mi][ni][1]);
                float2 v1 = make_float2(acc[mi][ni][2], acc[mi][ni][3]);
                *(float2*)(C + (size_t)r0 * N + cc)       = v0;
                *(float2*)(C + (size_t)(r0 + 8) * N + cc) = v1;
            }
        }
    }
}

// ---- GEMM kernels ----------------------------------------------------------
__global__ void __launch_bounds__(256, 2)
k_qkv()
{
    const size_t z = blockIdx.z;
    const uint16_t* wh = (const uint16_t*)g_wth + z * D * D;
    const uint16_t* wl = (const uint16_t*)g_wtl + z * D * D;
    uint32_t* oh = z == 0 ? g_qh : (z == 1 ? g_kh : g_vh);
    uint32_t* ol = z == 0 ? g_ql : (z == 1 ? g_kl : g_vl);
    gemm_core<false, true>((const uint16_t*)g_xh, (const uint16_t*)g_xl,
                           wh, wl, nullptr, oh, ol,
                           D, D, D, D, blockIdx.y, blockIdx.x);
}

__global__ void __launch_bounds__(256, 2)
k_scores()
{
    const int bm = blockIdx.y, bn = blockIdx.x;
    if (bn > bm) return;
    const size_t z = blockIdx.z;
    gemm_core<false, false>((const uint16_t*)g_qh + z * S * D,
                            (const uint16_t*)g_ql + z * S * D,
                            (const uint16_t*)g_kh + z * S * D,
                            (const uint16_t*)g_kl + z * S * D,
                            g_s + z * S * S, nullptr, nullptr,
                            S, D, D, D, bm, bn);
}

__global__ void __launch_bounds__(256, 2)
k_pv(float* __restrict__ out)
{
    const size_t z = blockIdx.z;
    gemm_core<true, false>((const uint16_t*)g_ph + z * S * S,
                           (const uint16_t*)g_pl + z * S * S,
                           (const uint16_t*)g_vth + z * D * S,
                           (const uint16_t*)g_vtl + z * D * S,
                           out + z * S * D, nullptr, nullptr,
                           D, S, S, S, blockIdx.y, blockIdx.x);
}

// ---- prep kernels ----------------------------------------------------------
__global__ void __launch_bounds__(256)
k_split_x(const float* __restrict__ x)
{
    const size_t n4 = (size_t)Bb * S * D / 4;
    for (size_t i = blockIdx.x * 256 + threadIdx.x; i < n4;
         i += (size_t)gridDim.x * 256) {
        float4 f = *(const float4*)(x + i * 4);
        uint32_t h0, l0, h1, l1;
        bf16_split2(f.x, f.y, h0, l0);
        bf16_split2(f.z, f.w, h1, l1);
        g_xh[i * 2] = h0;  g_xh[i * 2 + 1] = h1;
        g_xl[i * 2] = l0;  g_xl[i * 2 + 1] = l1;
    }
}

__global__ void __launch_bounds__(256)
k_wt(const float* __restrict__ wq, const float* __restrict__ wk,
     const float* __restrict__ wv)
{
    __shared__ float t[32][33];
    const float* src = blockIdx.z == 0 ? wq : (blockIdx.z == 1 ? wk : wv);
    uint16_t* dh = (uint16_t*)g_wth + (size_t)blockIdx.z * D * D;
    uint16_t* dl = (uint16_t*)g_wtl + (size_t)blockIdx.z * D * D;
    const int r0 = blockIdx.x << 5, c0 = blockIdx.y << 5;
    const int tx = threadIdx.x & 31, ty = threadIdx.x >> 5;
    #pragma unroll
    for (int i = 0; i < 32; i += 8)
        t[ty + i][tx] = src[(size_t)(r0 + ty + i) * D + c0 + tx];
    __syncthreads();
    #pragma unroll
    for (int i = 0; i < 32; i += 8) {
        float v = t[tx][ty + i];
        uint32_t hw, lw;
        bf16_split2(v, 0.f, hw, lw);
        const size_t idx = (size_t)(c0 + ty + i) * D + r0 + tx;
        dh[idx] = (uint16_t)hw;
        dl[idx] = (uint16_t)lw;
    }
}

__global__ void __launch_bounds__(256)
k_vt()
{
    __shared__ uint16_t th[32][34], tl[32][34];
    const uint16_t* sh = (const uint16_t*)g_vh + (size_t)blockIdx.z * S * D;
    const uint16_t* sl = (const uint16_t*)g_vl + (size_t)blockIdx.z * S * D;
    uint16_t* dh = (uint16_t*)g_vth + (size_t)blockIdx.z * D * S;
    uint16_t* dl = (uint16_t*)g_vtl + (size_t)blockIdx.z * D * S;
    const int s0 = blockIdx.x << 5, d0 = blockIdx.y << 5;
    const int tx = threadIdx.x & 31, ty = threadIdx.x >> 5;
    #pragma unroll
    for (int i = 0; i < 32; i += 8) {
        th[ty + i][tx] = sh[(size_t)(s0 + ty + i) * D + d0 + tx];
        tl[ty + i][tx] = sl[(size_t)(s0 + ty + i) * D + d0 + tx];
    }
    __syncthreads();
    #pragma unroll
    for (int i = 0; i < 32; i += 8) {
        const size_t idx = (size_t)(d0 + ty + i) * S + s0 + tx;
        dh[idx] = th[tx][ty + i];
        dl[idx] = tl[tx][ty + i];
    }
}

// ---- softmax: reads fp32 scores, writes hi/lo bf16 probabilities -----------
__global__ void __launch_bounds__(256)
softmax_causal()
{
    const int r = blockIdx.x;
    const int b = r >> 12;
    const int i = r & (S - 1);
    const float* row = g_s + ((size_t)b * S * S) + ((size_t)i * S);
    uint32_t* ph = g_ph + (((size_t)b * S * S) + ((size_t)i * S)) / 2;
    uint32_t* pl = g_pl + (((size_t)b * S * S) + ((size_t)i * S)) / 2;
    const int n  = i + 1;
    const int n4 = n & ~3;
    const int tid  = threadIdx.x;
    const int wid  = tid >> 5;
    const int lane = tid & 31;
    const float scale = 0.03125f;   // 1/sqrt(1024)

    __shared__ float shm[8], shs[8];

    auto upd = [&](float& m, float& s, float v) {
        if (v <= m) s += __expf((v - m) * scale);
        else { s = s * __expf((m - v) * scale) + 1.f; m = v; }
    };

    float m = -3.0e38f, s = 0.f;
    for (int j = tid * 4; j < n4; j += 1024) {
        float4 vv = *(const float4*)(row + j);
        upd(m, s, vv.x); upd(m, s, vv.y); upd(m, s, vv.z); upd(m, s, vv.w);
    }
    for (int j = n4 + tid; j < n; j += 256) upd(m, s, row[j]);

    #pragma unroll
    for (int o = 16; o > 0; o >>= 1) {
        float mo = __shfl_xor_sync(0xffffffffu, m, o);
        float so = __shfl_xor_sync(0xffffffffu, s, o);
        float M  = fmaxf(m, mo);
        s = s * __expf((m - M) * scale) + so * __expf((mo - M) * scale);
        m = M;
    }
    if (lane == 0) { shm[wid] = m; shs[wid] = s; }
    __syncthreads();
    float M = shm[0], Sm = shs[0];
    #pragma unroll
    for (int t = 1; t < 8; t++) {
        float mo = shm[t], so = shs[t];
        float Mx = fmaxf(M, mo);
        Sm = Sm * __expf((M - Mx) * scale) + so * __expf((mo - Mx) * scale);
        M = Mx;
    }
    const float inv = 1.0f / Sm;

    // write probabilities (hi/lo bf16), zero-filled to diagonal 128-block edge
    const int end = ((i >> 7) + 1) << 7;
    for (int j = tid * 2; j < end; j += 512) {
        float e0 = (j     < n) ? __expf((row[j]     - M) * scale) * inv : 0.f;
        float e1 = (j + 1 < n) ? __expf((row[j + 1] - M) * scale) * inv : 0.f;
        uint32_t hw, lw;
        bf16_split2(e0, e1, hw, lw);
        ph[j >> 1] = hw;
        pl[j >> 1] = lw;
    }
}

// ---------------------------------------------------------------------------
extern "C" void kernel_launch(void* const* d_in, const int* in_sizes, int n_in,
                              void* d_out, int out_size)
{
    const float* x  = (const float*)d_in[0];
    const float* Wq = (const float*)d_in[1];
    const float* Wk = (const float*)d_in[2];
    const float* Wv = (const float*)d_in[3];
    float* out = (float*)d_out;

    static bool init = false;
    if (!init) {
        cudaFuncSetAttribute(k_qkv,
                             cudaFuncAttributeMaxDynamicSharedMemorySize, SMEM_BYTES);
        cudaFuncSetAttribute(k_scores,
                             cudaFuncAttributeMaxDynamicSharedMemorySize, SMEM_BYTES);
        cudaFuncSetAttribute(k_pv,
                             cudaFuncAttributeMaxDynamicSharedMemorySize, SMEM_BYTES);
        init = true;
    }

    // 1) split inputs into hi/lo bf16
    k_split_x<<<2048, 256>>>(x);
    k_wt<<<dim3(D / 32, D / 32, 3), 256>>>(Wq, Wk, Wv);

    // 2) QKV projections (emit hi/lo bf16 q,k,v directly)
    k_qkv<<<dim3(D / BN, (Bb * S) / BM, 3), 256, SMEM_BYTES>>>();

    // 3) V^T (split)
    k_vt<<<dim3(S / 32, D / 32, Bb), 256>>>();

    // 4) scores = Q K^T (fp32 out, causal block skip)
    k_scores<<<dim3(S / BN, S / BM, Bb), 256, SMEM_BYTES>>>();

    // 5) softmax -> hi/lo bf16 P
    softmax_causal<<<Bb * S, 256>>>();

    // 6) out = P V
    k_pv<<<dim3(D / BN, S / BM, Bb), 256, SMEM_BYTES>>>(out);
}

// round 16
// speedup vs baseline: 1.6396x; 1.0093x over previous
#include <cuda_runtime.h>
#include <cstdint>

// ============================================================================
// CausalAttention, B=4, S=4096, D=1024, fp32 in/out.
// R16 = R15 (pre-split hi/lo bf16 operands in gmem, cp.async 3-stage pipeline,
// ldmatrix.x4, bf16x3 mma.sync, register-lean consumer, 2 CTAs/SM) with the
// chunk loop reduced to ONE barrier: with 3 stages, the stage written at
// iteration ic was consumed at ic-1, and the top-of-loop barrier already
// orders that — the tail barrier was redundant and is removed.
// ============================================================================

static constexpr int Bb = 4;
static constexpr int S  = 4096;
static constexpr int D  = 1024;
static constexpr int BM = 128;
static constexpr int BN = 128;
static constexpr int BK = 32;                 // K elems per chunk (16 words)

static constexpr int STAGE_BYTES = 32768;     // Ah,Al,Bh,Bl tiles (8 KB each)
static constexpr int NSTAGE      = 3;
static constexpr int SMEM_BYTES  = NSTAGE * STAGE_BYTES;  // 98304

// gmem scratch (hi/lo bf16 stored as u32 words = 2 elems; fp32 scores)
static __device__ uint32_t g_xh [(size_t)Bb * S * D / 2];
static __device__ uint32_t g_xl [(size_t)Bb * S * D / 2];
static __device__ uint32_t g_wth[(size_t)3 * D * D / 2];
static __device__ uint32_t g_wtl[(size_t)3 * D * D / 2];
static __device__ uint32_t g_qh [(size_t)Bb * S * D / 2];
static __device__ uint32_t g_ql [(size_t)Bb * S * D / 2];
static __device__ uint32_t g_kh [(size_t)Bb * S * D / 2];
static __device__ uint32_t g_kl [(size_t)Bb * S * D / 2];
static __device__ uint32_t g_vh [(size_t)Bb * S * D / 2];
static __device__ uint32_t g_vl [(size_t)Bb * S * D / 2];
static __device__ uint32_t g_vth[(size_t)Bb * D * S / 2];
static __device__ uint32_t g_vtl[(size_t)Bb * D * S / 2];
static __device__ float    g_s  [(size_t)Bb * S * S];
static __device__ uint32_t g_ph [(size_t)Bb * S * S / 2];
static __device__ uint32_t g_pl [(size_t)Bb * S * S / 2];

// ---------------------------------------------------------------------------
__device__ __forceinline__ uint32_t tile_addr(uint32_t row, uint32_t w) {
    const uint32_t line = row >> 1;
    const uint32_t off  = ((row & 1u) << 4) + w;
    return line * 32u + (off ^ ((line & 7u) << 2));
}
__device__ __forceinline__ uint32_t smem_u32(const void* p) {
    uint32_t a;
    asm("{ .reg .u64 t; cvta.to.shared.u64 t, %1; cvt.u32.u64 %0, t; }"
        : "=r"(a) : "l"(p));
    return a;
}
__device__ __forceinline__ void ldsm_x4(uint32_t (&r)[4], uint32_t saddr) {
    asm volatile("ldmatrix.sync.aligned.m8n8.x4.shared.b16 {%0,%1,%2,%3}, [%4];"
                 : "=r"(r[0]), "=r"(r[1]), "=r"(r[2]), "=r"(r[3])
                 : "r"(saddr));
}
__device__ __forceinline__ void cp16(uint32_t dst, const void* src) {
    asm volatile("cp.async.cg.shared.global [%0], [%1], 16;"
                 :: "r"(dst), "l"(src));
}
__device__ __forceinline__ void cp_commit() {
    asm volatile("cp.async.commit_group;" ::: "memory");
}
template<int NN>
__device__ __forceinline__ void cp_wait() {
    asm volatile("cp.async.wait_group %0;" :: "n"(NN) : "memory");
}
// split (x0, x1) into hi/lo bf16x2 words (lower 16 bits = x0)
__device__ __forceinline__ void bf16_split2(float x0, float x1,
                                            uint32_t& hw, uint32_t& lw) {
    asm("cvt.rn.bf16x2.f32 %0, %1, %2;" : "=r"(hw) : "f"(x1), "f"(x0));
    const float h0 = __uint_as_float(hw << 16);
    const float h1 = __uint_as_float(hw & 0xffff0000u);
    const float r0 = x0 - h0;
    const float r1 = x1 - h1;
    asm("cvt.rn.bf16x2.f32 %0, %1, %2;" : "=r"(lw) : "f"(r1), "f"(r0));
}
__device__ __forceinline__ void mma_bf16(float (&d)[4], const uint32_t (&a)[4],
                                         uint32_t b0, uint32_t b1) {
    asm("mma.sync.aligned.m16n8k16.row.col.f32.bf16.bf16.f32 "
        "{%0,%1,%2,%3}, {%4,%5,%6,%7}, {%8,%9}, {%0,%1,%2,%3};"
        : "+f"(d[0]), "+f"(d[1]), "+f"(d[2]), "+f"(d[3])
        : "r"(a[0]), "r"(a[1]), "r"(a[2]), "r"(a[3]), "r"(b0), "r"(b1));
}

// ---------------------------------------------------------------------------
// C[bm,bn tile] = A * B^T; A,B are hi/lo bf16 element arrays (A: [M][K] lda,
// B: [N][K] ldb). SPLIT_OUT: write hi/lo bf16 words to Ch/Cl. KLIM: K limited
// to (bm+1)*BM. 256 threads, register-lean (2 CTAs/SM).
// ---------------------------------------------------------------------------
template<bool KLIM, bool SPLIT_OUT>
__device__ __forceinline__ void
gemm_core(const uint16_t* __restrict__ Ah, const uint16_t* __restrict__ Al,
          const uint16_t* __restrict__ Bh, const uint16_t* __restrict__ Bl,
          float* __restrict__ C, uint32_t* __restrict__ Ch,
          uint32_t* __restrict__ Cl,
          int N, int K, int lda, int ldb, int bm, int bn)
{
    const int kEnd   = KLIM ? min(K, (bm + 1) * BM) : K;
    const int nchunk = kEnd / BK;

    extern __shared__ uint32_t sm[];
    const uint32_t smb = smem_u32(sm);

    const int tid  = threadIdx.x;
    const int wid  = tid >> 5;
    const int wm   = wid & 3;               // 4 warps along M
    const int wn   = wid >> 2;              // 2 warps along N
    const int lane = tid & 31;
    const int g    = lane >> 2;
    const int c    = lane & 3;
    const int l8   = lane & 7;
    const int lm   = lane >> 3;

    uint32_t relA[2][2], relB0[2];
    #pragma unroll
    for (int mi = 0; mi < 2; mi++) {
        const uint32_t row = wm * 32 + mi * 16 + ((lm & 1) << 3) + l8;
        const uint32_t w   = (lm >> 1) << 2;
        relA[mi][0] = tile_addr(row, w) * 4u;
        relA[mi][1] = tile_addr(row, w + 8) * 4u;
    }
    {
        const uint32_t row = wn * 64 + ((lm >> 1) << 3) + l8;
        const uint32_t w   = (lm & 1) << 2;
        relB0[0] = tile_addr(row, w) * 4u;
        relB0[1] = tile_addr(row, w + 8) * 4u;
    }

    // staging map: thread t -> row t>>1, half h = t&1 (16 elems = 2 x 16B)
    const int row = tid >> 1;
    const int h   = tid & 1;
    const uint32_t d0 = tile_addr(row, h * 8) * 4u;
    const uint32_t d1 = (tile_addr(row, h * 8) ^ 4u) * 4u;
    const uint16_t* sAh = Ah + (size_t)(bm * BM + row) * lda + h * 16;
    const uint16_t* sAl = Al + (size_t)(bm * BM + row) * lda + h * 16;
    const uint16_t* sBh = Bh + (size_t)(bn * BN + row) * ldb + h * 16;
    const uint16_t* sBl = Bl + (size_t)(bn * BN + row) * ldb + h * 16;

    auto issue_stage = [&](int sidx, int kc) {
        const uint32_t b = smb + sidx * STAGE_BYTES;
        cp16(b + d0,                       sAh + kc);
        cp16(b + d1,                       sAh + kc + 8);
        cp16(b + STAGE_BYTES / 4 + d0,     sAl + kc);       // +8192 B
        cp16(b + STAGE_BYTES / 4 + d1,     sAl + kc + 8);
        cp16(b + STAGE_BYTES / 2 + d0,     sBh + kc);       // +16384 B
        cp16(b + STAGE_BYTES / 2 + d1,     sBh + kc + 8);
        cp16(b + 3 * STAGE_BYTES / 4 + d0, sBl + kc);       // +24576 B
        cp16(b + 3 * STAGE_BYTES / 4 + d1, sBl + kc + 8);
    };

    // prologue: 2 chunks in flight
    issue_stage(0, 0);
    cp_commit();
    if (nchunk > 1) issue_stage(1, BK);
    cp_commit();

    float acc[2][8][4];
    #pragma unroll
    for (int mi = 0; mi < 2; mi++)
        #pragma unroll
        for (int ni = 0; ni < 8; ni++)
            #pragma unroll
            for (int q = 0; q < 4; q++) acc[mi][ni][q] = 0.f;

    int sidx = 0;
    for (int ic = 0; ic < nchunk; ic++) {
        cp_wait<1>();                       // group ic complete (this thread)
        // ONE barrier per chunk. It orders (a) all threads' cp.async stores
        // for chunk ic before any fragment read, and (b) all threads'
        // iteration ic-1 consumption before the writes issued below into
        // stage (ic+2)%3 == (ic-1)%3.
        __syncthreads();

        if (ic + 2 < nchunk) {
            int ns = sidx + 2;
            if (ns >= NSTAGE) ns -= NSTAGE;
            issue_stage(ns, (ic + 2) * BK);
        }
        cp_commit();                        // one group per iteration, always

        const uint32_t base = smb + sidx * STAGE_BYTES;
        const uint32_t bAh = base;
        const uint32_t bAl = base + STAGE_BYTES / 4;
        const uint32_t bBh = base + STAGE_BYTES / 2;
        const uint32_t bBl = base + 3 * STAGE_BYTES / 4;

        #pragma unroll
        for (int kt = 0; kt < 2; kt++) {
            uint32_t ah[2][4], al[2][4];
            #pragma unroll
            for (int mi = 0; mi < 2; mi++) {
                ldsm_x4(ah[mi], bAh + relA[mi][kt]);
                ldsm_x4(al[mi], bAl + relA[mi][kt]);
            }
            #pragma unroll
            for (int p = 0; p < 4; p++) {
                uint32_t bh[4], bl[4];
                ldsm_x4(bh, bBh + relB0[kt] + p * 1024u);
                ldsm_x4(bl, bBl + relB0[kt] + p * 1024u);
                const int n0 = 2 * p, n1 = 2 * p + 1;
                // grouped by split term; 4 distinct accumulators per group
                mma_bf16(acc[0][n0], ah[0], bh[0], bh[1]);
                mma_bf16(acc[0][n1], ah[0], bh[2], bh[3]);
                mma_bf16(acc[1][n0], ah[1], bh[0], bh[1]);
                mma_bf16(acc[1][n1], ah[1], bh[2], bh[3]);
                mma_bf16(acc[0][n0], al[0], bh[0], bh[1]);
                mma_bf16(acc[0][n1], al[0], bh[2], bh[3]);
                mma_bf16(acc[1][n0], al[1], bh[0], bh[1]);
                mma_bf16(acc[1][n1], al[1], bh[2], bh[3]);
                mma_bf16(acc[0][n0], ah[0], bl[0], bl[1]);
                mma_bf16(acc[0][n1], ah[0], bl[2], bl[3]);
                mma_bf16(acc[1][n0], ah[1], bl[0], bl[1]);
                mma_bf16(acc[1][n1], ah[1], bl[2], bl[3]);
            }
        }

        if (++sidx == NSTAGE) sidx = 0;
    }

    // epilogue
    #pragma unroll
    for (int mi = 0; mi < 2; mi++) {
        const int r0 = bm * BM + wm * 32 + mi * 16 + g;
        #pragma unroll
        for (int ni = 0; ni < 8; ni++) {
            const int cc = bn * BN + wn * 64 + ni * 8 + c * 2;
            if (SPLIT_OUT) {
                uint32_t hw, lw;
                bf16_split2(acc[mi][ni][0], acc[mi][ni][1], hw, lw);
                Ch[((size_t)r0 * N + cc) >> 1] = hw;
                Cl[((size_t)r0 * N + cc) >> 1] = lw;
                bf16_split2(acc[mi][ni][2], acc[mi][ni][3], hw, lw);
                Ch[((size_t)(r0 + 8) * N + cc) >> 1] = hw;
                Cl[((size_t)(r0 + 8) * N + cc) >> 1] = lw;
            } else {
                float2 v0 = make_float2(acc[mi][ni][0], acc[mi][ni][1]);
                float2 v1 = make_float2(acc[mi][ni][2], acc[mi][ni][3]);
                *(float2*)(C + (size_t)r0 * N + cc)       = v0;
                *(float2*)(C + (size_t)(r0 + 8) * N + cc) = v1;
            }
        }
    }
}

// ---- GEMM kernels ----------------------------------------------------------
__global__ void __launch_bounds__(256, 2)
k_qkv()
{
    const size_t z = blockIdx.z;
    const uint16_t* wh = (const uint16_t*)g_wth + z * D * D;
    const uint16_t* wl = (const uint16_t*)g_wtl + z * D * D;
    uint32_t* oh = z == 0 ? g_qh : (z == 1 ? g_kh : g_vh);
    uint32_t* ol = z == 0 ? g_ql : (z == 1 ? g_kl : g_vl);
    gemm_core<false, true>((const uint16_t*)g_xh, (const uint16_t*)g_xl,
                           wh, wl, nullptr, oh, ol,
                           D, D, D, D, blockIdx.y, blockIdx.x);
}

__global__ void __launch_bounds__(256, 2)
k_scores()
{
    const int bm = blockIdx.y, bn = blockIdx.x;
    if (bn > bm) return;
    const size_t z = blockIdx.z;
    gemm_core<false, false>((const uint16_t*)g_qh + z * S * D,
                            (const uint16_t*)g_ql + z * S * D,
                            (const uint16_t*)g_kh + z * S * D,
                            (const uint16_t*)g_kl + z * S * D,
                            g_s + z * S * S, nullptr, nullptr,
                            S, D, D, D, bm, bn);
}

__global__ void __launch_bounds__(256, 2)
k_pv(float* __restrict__ out)
{
    const size_t z = blockIdx.z;
    gemm_core<true, false>((const uint16_t*)g_ph + z * S * S,
                           (const uint16_t*)g_pl + z * S * S,
                           (const uint16_t*)g_vth + z * D * S,
                           (const uint16_t*)g_vtl + z * D * S,
                           out + z * S * D, nullptr, nullptr,
                           D, S, S, S, blockIdx.y, blockIdx.x);
}

// ---- prep kernels ----------------------------------------------------------
__global__ void __launch_bounds__(256)
k_split_x(const float* __restrict__ x)
{
    const size_t n4 = (size_t)Bb * S * D / 4;
    for (size_t i = blockIdx.x * 256 + threadIdx.x; i < n4;
         i += (size_t)gridDim.x * 256) {
        float4 f = *(const float4*)(x + i * 4);
        uint32_t h0, l0, h1, l1;
        bf16_split2(f.x, f.y, h0, l0);
        bf16_split2(f.z, f.w, h1, l1);
        g_xh[i * 2] = h0;  g_xh[i * 2 + 1] = h1;
        g_xl[i * 2] = l0;  g_xl[i * 2 + 1] = l1;
    }
}

__global__ void __launch_bounds__(256)
k_wt(const float* __restrict__ wq, const float* __restrict__ wk,
     const float* __restrict__ wv)
{
    __shared__ float t[32][33];
    const float* src = blockIdx.z == 0 ? wq : (blockIdx.z == 1 ? wk : wv);
    uint16_t* dh = (uint16_t*)g_wth + (size_t)blockIdx.z * D * D;
    uint16_t* dl = (uint16_t*)g_wtl + (size_t)blockIdx.z * D * D;
    const int r0 = blockIdx.x << 5, c0 = blockIdx.y << 5;
    const int tx = threadIdx.x & 31, ty = threadIdx.x >> 5;
    #pragma unroll
    for (int i = 0; i < 32; i += 8)
        t[ty + i][tx] = src[(size_t)(r0 + ty + i) * D + c0 + tx];
    __syncthreads();
    #pragma unroll
    for (int i = 0; i < 32; i += 8) {
        float v = t[tx][ty + i];
        uint32_t hw, lw;
        bf16_split2(v, 0.f, hw, lw);
        const size_t idx = (size_t)(c0 + ty + i) * D + r0 + tx;
        dh[idx] = (uint16_t)hw;
        dl[idx] = (uint16_t)lw;
    }
}

__global__ void __launch_bounds__(256)
k_vt()
{
    __shared__ uint16_t th[32][34], tl[32][34];
    const uint16_t* sh = (const uint16_t*)g_vh + (size_t)blockIdx.z * S * D;
    const uint16_t* sl = (const uint16_t*)g_vl + (size_t)blockIdx.z * S * D;
    uint16_t* dh = (uint16_t*)g_vth + (size_t)blockIdx.z * D * S;
    uint16_t* dl = (uint16_t*)g_vtl + (size_t)blockIdx.z * D * S;
    const int s0 = blockIdx.x << 5, d0 = blockIdx.y << 5;
    const int tx = threadIdx.x & 31, ty = threadIdx.x >> 5;
    #pragma unroll
    for (int i = 0; i < 32; i += 8) {
        th[ty + i][tx] = sh[(size_t)(s0 + ty + i) * D + d0 + tx];
        tl[ty + i][tx] = sl[(size_t)(s0 + ty + i) * D + d0 + tx];
    }
    __syncthreads();
    #pragma unroll
    for (int i = 0; i < 32; i += 8) {
        const size_t idx = (size_t)(d0 + ty + i) * S + s0 + tx;
        dh[idx] = th[tx][ty + i];
        dl[idx] = tl[tx][ty + i];
    }
}

// ---- softmax: reads fp32 scores, writes hi/lo bf16 probabilities -----------
__global__ void __launch_bounds__(256)
softmax_causal()
{
    const int r = blockIdx.x;
    const int b = r >> 12;
    const int i = r & (S - 1);
    const float* row = g_s + ((size_t)b * S * S) + ((size_t)i * S);
    uint32_t* ph = g_ph + (((size_t)b * S * S) + ((size_t)i * S)) / 2;
    uint32_t* pl = g_pl + (((size_t)b * S * S) + ((size_t)i * S)) / 2;
    const int n  = i + 1;
    const int n4 = n & ~3;
    const int tid  = threadIdx.x;
    const int wid  = tid >> 5;
    const int lane = tid & 31;
    const float scale = 0.03125f;   // 1/sqrt(1024)

    __shared__ float shm[8], shs[8];

    auto upd = [&](float& m, float& s, float v) {
        if (v <= m) s += __expf((v - m) * scale);
        else { s = s * __expf((m - v) * scale) + 1.f; m = v; }
    };

    float m = -3.0e38f, s = 0.f;
    for (int j = tid * 4; j < n4; j += 1024) {
        float4 vv = *(const float4*)(row + j);
        upd(m, s, vv.x); upd(m, s, vv.y); upd(m, s, vv.z); upd(m, s, vv.w);
    }
    for (int j = n4 + tid; j < n; j += 256) upd(m, s, row[j]);

    #pragma unroll
    for (int o = 16; o > 0; o >>= 1) {
        float mo = __shfl_xor_sync(0xffffffffu, m, o);
        float so = __shfl_xor_sync(0xffffffffu, s, o);
        float M  = fmaxf(m, mo);
        s = s * __expf((m - M) * scale) + so * __expf((mo - M) * scale);
        m = M;
    }
    if (lane == 0) { shm[wid] = m; shs[wid] = s; }
    __syncthreads();
    float M = shm[0], Sm = shs[0];
    #pragma unroll
    for (int t = 1; t < 8; t++) {
        float mo = shm[t], so = shs[t];
        float Mx = fmaxf(M, mo);
        Sm = Sm * __expf((M - Mx) * scale) + so * __expf((mo - Mx) * scale);
        M = Mx;
    }
    const float inv = 1.0f / Sm;

    // write probabilities (hi/lo bf16), zero-filled to diagonal 128-block edge
    const int end = ((i >> 7) + 1) << 7;
    for (int j = tid * 2; j < end; j += 512) {
        float e0 = (j     < n) ? __expf((row[j]     - M) * scale) * inv : 0.f;
        float e1 = (j + 1 < n) ? __expf((row[j + 1] - M) * scale) * inv : 0.f;
        uint32_t hw, lw;
        bf16_split2(e0, e1, hw, lw);
        ph[j >> 1] = hw;
        pl[j >> 1] = lw;
    }
}

// ---------------------------------------------------------------------------
extern "C" void kernel_launch(void* const* d_in, const int* in_sizes, int n_in,
                              void* d_out, int out_size)
{
    const float* x  = (const float*)d_in[0];
    const float* Wq = (const float*)d_in[1];
    const float* Wk = (const float*)d_in[2];
    const float* Wv = (const float*)d_in[3];
    float* out = (float*)d_out;

    static bool init = false;
    if (!init) {
        cudaFuncSetAttribute(k_qkv,
                             cudaFuncAttributeMaxDynamicSharedMemorySize, SMEM_BYTES);
        cudaFuncSetAttribute(k_scores,
                             cudaFuncAttributeMaxDynamicSharedMemorySize, SMEM_BYTES);
        cudaFuncSetAttribute(k_pv,
                             cudaFuncAttributeMaxDynamicSharedMemorySize, SMEM_BYTES);
        init = true;
    }

    // 1) split inputs into hi/lo bf16
    k_split_x<<<2048, 256>>>(x);
    k_wt<<<dim3(D / 32, D / 32, 3), 256>>>(Wq, Wk, Wv);

    // 2) QKV projections (emit hi/lo bf16 q,k,v directly)
    k_qkv<<<dim3(D / BN, (Bb * S) / BM, 3), 256, SMEM_BYTES>>>();

    // 3) V^T (split)
    k_vt<<<dim3(S / 32, D / 32, Bb), 256>>>();

    // 4) scores = Q K^T (fp32 out, causal block skip)
    k_scores<<<dim3(S / BN, S / BM, Bb), 256, SMEM_BYTES>>>();

    // 5) softmax -> hi/lo bf16 P
    softmax_causal<<<Bb * S, 256>>>();

    // 6) out = P V
    k_pv<<<dim3(D / BN, S / BM, Bb), 256, SMEM_BYTES>>>(out);
}